// round 5
// baseline (speedup 1.0000x reference)
#include <cuda_runtime.h>

// Problem constants (from setup_inputs: B=4, N=256, F=128)
#define B_  4
#define N_  256
#define F_  128
#define BN_ (B_*N_)
#define TJ  32

// ---------------- device scratch (static: no allocation allowed) ----------------
__device__ float g_hln[BN_*F_];   // layernormed h
__device__ float g_xln[BN_*3];    // layernormed x
__device__ float g_Ae[BN_*F_];    // edg1_w[:, :F] @ h_ln + edg1_b
__device__ float g_Be[BN_*F_];    // edg1_w[:, F:2F] @ h_ln
__device__ float g_Ac[BN_*F_];    // cor1 analogues
__device__ float g_Bc[BN_*F_];
__device__ float g_agg[BN_*F_];   // sum_j e*m
__device__ float g_w2eT[F_*F_];   // edg2_w transposed (k-major)
__device__ float g_w2cT[F_*F_];   // cor2_w transposed

__device__ __forceinline__ float siluf(float z) { return z / (1.f + __expf(-z)); }

// ---------------- kernel: transpose the two FxF hidden weights ----------------
__global__ void transpose_k(const float* __restrict__ e2, const float* __restrict__ c2) {
    int k = blockIdx.x, f = threadIdx.x;
    g_w2eT[k*F_ + f] = e2[f*F_ + k];
    g_w2cT[k*F_ + f] = c2[f*F_ + k];
}

// ---------------- kernel: per-node precompute (LN + layer-1 decomposition) ----------------
__global__ void pre_k(const float* __restrict__ x,  const float* __restrict__ h,
                      const float* __restrict__ lnh_w, const float* __restrict__ lnh_b,
                      const float* __restrict__ lnx_w, const float* __restrict__ lnx_b,
                      const float* __restrict__ e1w, const float* __restrict__ e1b,
                      const float* __restrict__ c1w, const float* __restrict__ c1b) {
    int row = blockIdx.x;
    int f   = threadIdx.x;
    __shared__ float hln[F_];
    __shared__ float red[4];

    float v = h[row*F_ + f];
    float s = v;
    #pragma unroll
    for (int o = 16; o; o >>= 1) s += __shfl_xor_sync(0xffffffffu, s, o);
    int lane = f & 31, wp = f >> 5;
    if (lane == 0) red[wp] = s;
    __syncthreads();
    float mean = (red[0] + red[1] + red[2] + red[3]) * (1.f / F_);
    float d = v - mean;
    float s2 = d * d;
    #pragma unroll
    for (int o = 16; o; o >>= 1) s2 += __shfl_xor_sync(0xffffffffu, s2, o);
    __syncthreads();               // everyone has read red[] for mean
    if (lane == 0) red[wp] = s2;
    __syncthreads();
    float var  = (red[0] + red[1] + red[2] + red[3]) * (1.f / F_);
    float rstd = rsqrtf(var + 1e-5f);
    float hl = d * rstd * lnh_w[f] + lnh_b[f];
    hln[f] = hl;
    g_hln[row*F_ + f] = hl;

    if (f == 0) {  // layernorm of x over 3 components
        float a0 = x[row*3+0], a1 = x[row*3+1], a2 = x[row*3+2];
        float m  = (a0 + a1 + a2) * (1.f/3.f);
        float d0 = a0 - m, d1 = a1 - m, d2 = a2 - m;
        float vr = (d0*d0 + d1*d1 + d2*d2) * (1.f/3.f);
        float rs = rsqrtf(vr + 1e-5f);
        g_xln[row*3+0] = d0*rs*lnx_w[0] + lnx_b[0];
        g_xln[row*3+1] = d1*rs*lnx_w[1] + lnx_b[1];
        g_xln[row*3+2] = d2*rs*lnx_w[2] + lnx_b[2];
    }
    __syncthreads();

    // A/B decomposition of layer-1 (weight rows have 2F+2 = 258 columns)
    float ae = e1b[f], be = 0.f, ac = c1b[f], bc = 0.f;
    const float* er = e1w + f*258;
    const float* cr = c1w + f*258;
    #pragma unroll 4
    for (int k = 0; k < F_; k++) {
        float hk = hln[k];
        ae += er[k]       * hk;
        be += er[128 + k] * hk;
        ac += cr[k]       * hk;
        bc += cr[128 + k] * hk;
    }
    g_Ae[row*F_+f] = ae; g_Be[row*F_+f] = be;
    g_Ac[row*F_+f] = ac; g_Bc[row*F_+f] = bc;
}

// ---------------- the pair kernel: one CTA per (b,i) ----------------
// SMEM floats: w2e 16384 | w2c 16384 | m1e 4096 | m1c 4096 | dsq 32 | r0 32
//              shift 96 | xi 8 | aggred 1024 | csum 24   = 42176 floats = 168704 B
#define PAIR_SMEM_BYTES (42176 * 4)

__global__ __launch_bounds__(256, 1)
void pair_k(const float* __restrict__ x,   const float* __restrict__ x0,
            const float* __restrict__ e1w, const float* __restrict__ c1w,
            const float* __restrict__ e2b, const float* __restrict__ c2b,
            const float* __restrict__ eiw, const float* __restrict__ eib,
            const float* __restrict__ c3w, const float* __restrict__ c3b,
            float* __restrict__ out_x) {
    extern __shared__ float sm[];
    float* w2e      = sm;                  // [128][128] k-major
    float* w2c      = w2e + F_*F_;
    float* m1e      = w2c + F_*F_;         // [TJ][128]
    float* m1c      = m1e + TJ*F_;
    float* dsq_sh   = m1c + TJ*F_;         // [TJ]
    float* r0_sh    = dsq_sh + TJ;         // [TJ]
    float* shift_sh = r0_sh + TJ;          // [TJ][3]
    float* xi_sh    = shift_sh + TJ*3;     // x_i (3) at [0..2], x0_i (3) at [4..6]
    float* aggred   = xi_sh + 8;           // [8][128]
    float* csum_sh  = aggred + 8*F_;       // [8][3]

    int tid  = threadIdx.x;
    int rowI = blockIdx.x;
    int b    = rowI >> 8;
    int i    = rowI & 255;

    // stage both transposed weight matrices into SMEM (vectorized, conflict-free)
    for (int idx = tid; idx < F_*F_/4; idx += 256) {
        ((float4*)w2e)[idx] = ((const float4*)g_w2eT)[idx];
        ((float4*)w2c)[idx] = ((const float4*)g_w2cT)[idx];
    }
    if (tid < 3) {
        xi_sh[tid]     = x [rowI*3 + tid];
        xi_sh[4 + tid] = x0[rowI*3 + tid];
    }

    // per-feature constants for phase-1 (thread t handles f = t & 127)
    int f = tid & 127;
    float ae  = g_Ae[rowI*F_ + f];
    float ac  = g_Ac[rowI*F_ + f];
    float wed = e1w[f*258 + 256], wer = e1w[f*258 + 257];
    float wcd = c1w[f*258 + 256], wcr = c1w[f*258 + 257];

    // GEMM tiling: warp tj owns 4 j's, lane tf owns 4 f's (f = tf*4..tf*4+3)
    int tj = tid >> 5, tf = tid & 31;
    float4 b2e = ((const float4*)e2b)[tf];
    float4 b2c = ((const float4*)c2b)[tf];
    float4 wie = ((const float4*)eiw)[tf];
    float4 w3v = ((const float4*)c3w)[tf];
    float  bie = eib[0], b3 = c3b[0];

    float4 aggr = make_float4(0.f, 0.f, 0.f, 0.f);
    float  csum_acc = 0.f;

    __syncthreads();

    for (int j0 = 0; j0 < N_; j0 += TJ) {
        // ---- phase 0: per-j geometric scalars ----
        if (tid < TJ) {
            int j = j0 + tid;
            const float* xj = x + (b*N_ + j)*3;
            float dx = xi_sh[0] - xj[0];
            float dy = xi_sh[1] - xj[1];
            float dz = xi_sh[2] - xj[2];
            float ds = dx*dx + dy*dy + dz*dz;
            float r  = sqrtf(ds);
            float ri = 1.f / (r + 1.f);
            dsq_sh[tid] = ds;
            shift_sh[tid*3+0] = dx * ri;
            shift_sh[tid*3+1] = dy * ri;
            shift_sh[tid*3+2] = dz * ri;
            const float* x0j = x0 + (b*N_ + j)*3;
            float ex = xi_sh[4] - x0j[0];
            float ey = xi_sh[5] - x0j[1];
            float ez = xi_sh[6] - x0j[2];
            r0_sh[tid] = sqrtf(ex*ex + ey*ey + ez*ez);
        }
        __syncthreads();

        // ---- phase 1: layer-1 (decomposed) + silu -> m1 tiles ----
        {
            int jj0 = tid >> 7;   // threads 0..127 do even jj, 128..255 odd jj
            for (int jj = jj0; jj < TJ; jj += 2) {
                int j = j0 + jj;
                float be = g_Be[(b*N_ + j)*F_ + f];
                float bc = g_Bc[(b*N_ + j)*F_ + f];
                float ds = dsq_sh[jj], rr = r0_sh[jj];
                float ze = ae + be + wed*ds + wer*rr;
                float zc = ac + bc + wcd*ds + wcr*rr;
                m1e[jj*F_ + f] = siluf(ze);
                m1c[jj*F_ + f] = siluf(zc);
            }
        }
        __syncthreads();

        // ---- phase 2a: edge GEMM (32x128 @ 128x128), 4j x 4f per thread ----
        {
            float4 acc[4];
            acc[0] = b2e; acc[1] = b2e; acc[2] = b2e; acc[3] = b2e;
            #pragma unroll 2
            for (int k = 0; k < F_; k += 4) {
                float4 a0 = *(const float4*)&m1e[(tj*4+0)*F_ + k];
                float4 a1 = *(const float4*)&m1e[(tj*4+1)*F_ + k];
                float4 a2 = *(const float4*)&m1e[(tj*4+2)*F_ + k];
                float4 a3 = *(const float4*)&m1e[(tj*4+3)*F_ + k];
                #pragma unroll
                for (int kk = 0; kk < 4; kk++) {
                    float4 w = *(const float4*)&w2e[(k+kk)*F_ + tf*4];
                    float v0 = ((const float*)&a0)[kk];
                    float v1 = ((const float*)&a1)[kk];
                    float v2 = ((const float*)&a2)[kk];
                    float v3 = ((const float*)&a3)[kk];
                    acc[0].x += v0*w.x; acc[0].y += v0*w.y; acc[0].z += v0*w.z; acc[0].w += v0*w.w;
                    acc[1].x += v1*w.x; acc[1].y += v1*w.y; acc[1].z += v1*w.z; acc[1].w += v1*w.w;
                    acc[2].x += v2*w.x; acc[2].y += v2*w.y; acc[2].z += v2*w.z; acc[2].w += v2*w.w;
                    acc[3].x += v3*w.x; acc[3].y += v3*w.y; acc[3].z += v3*w.z; acc[3].w += v3*w.w;
                }
            }
            #pragma unroll
            for (int jj = 0; jj < 4; jj++) {
                float m0 = siluf(acc[jj].x);
                float m1 = siluf(acc[jj].y);
                float m2 = siluf(acc[jj].z);
                float m3 = siluf(acc[jj].w);
                float p = m0*wie.x + m1*wie.y + m2*wie.z + m3*wie.w;
                #pragma unroll
                for (int o = 16; o; o >>= 1) p += __shfl_xor_sync(0xffffffffu, p, o);
                float e = 1.f / (1.f + __expf(-(p + bie)));
                int j = j0 + tj*4 + jj;
                if (j == i) e = 0.f;                      // (1 - eye) mask
                aggr.x += e*m0; aggr.y += e*m1; aggr.z += e*m2; aggr.w += e*m3;
            }
        }

        // ---- phase 2b: coordinate GEMM ----
        {
            float4 acc[4];
            acc[0] = b2c; acc[1] = b2c; acc[2] = b2c; acc[3] = b2c;
            #pragma unroll 2
            for (int k = 0; k < F_; k += 4) {
                float4 a0 = *(const float4*)&m1c[(tj*4+0)*F_ + k];
                float4 a1 = *(const float4*)&m1c[(tj*4+1)*F_ + k];
                float4 a2 = *(const float4*)&m1c[(tj*4+2)*F_ + k];
                float4 a3 = *(const float4*)&m1c[(tj*4+3)*F_ + k];
                #pragma unroll
                for (int kk = 0; kk < 4; kk++) {
                    float4 w = *(const float4*)&w2c[(k+kk)*F_ + tf*4];
                    float v0 = ((const float*)&a0)[kk];
                    float v1 = ((const float*)&a1)[kk];
                    float v2 = ((const float*)&a2)[kk];
                    float v3 = ((const float*)&a3)[kk];
                    acc[0].x += v0*w.x; acc[0].y += v0*w.y; acc[0].z += v0*w.z; acc[0].w += v0*w.w;
                    acc[1].x += v1*w.x; acc[1].y += v1*w.y; acc[1].z += v1*w.z; acc[1].w += v1*w.w;
                    acc[2].x += v2*w.x; acc[2].y += v2*w.y; acc[2].z += v2*w.z; acc[2].w += v2*w.w;
                    acc[3].x += v3*w.x; acc[3].y += v3*w.y; acc[3].z += v3*w.z; acc[3].w += v3*w.w;
                }
            }
            #pragma unroll
            for (int jj = 0; jj < 4; jj++) {
                float m0 = siluf(acc[jj].x);
                float m1 = siluf(acc[jj].y);
                float m2 = siluf(acc[jj].z);
                float m3 = siluf(acc[jj].w);
                float p = m0*w3v.x + m1*w3v.y + m2*w3v.z + m3*w3v.w;
                #pragma unroll
                for (int o = 16; o; o >>= 1) p += __shfl_xor_sync(0xffffffffu, p, o);
                float cw = p + b3;                        // no activation on cor3
                float sv = (tf < 3) ? shift_sh[(tj*4+jj)*3 + tf] : 0.f;
                csum_acc += cw * sv;                      // diagonal: shift == 0 exactly
            }
        }
        __syncthreads();   // protect m1/scalars before next tile overwrites
    }

    // ---- final reductions across the 8 warps ----
    *((float4*)&aggred[tj*F_ + tf*4]) = aggr;
    if (tf < 3) csum_sh[tj*3 + tf] = csum_acc;
    __syncthreads();
    if (tid < F_) {
        float s = 0.f;
        #pragma unroll
        for (int w = 0; w < 8; w++) s += aggred[w*F_ + tid];
        g_agg[rowI*F_ + tid] = s;
    }
    if (tid < 3) {
        float s = 0.f;
        #pragma unroll
        for (int w = 0; w < 8; w++) s += csum_sh[w*3 + tid];
        out_x[rowI*3 + tid] = g_xln[rowI*3 + tid] + s;
    }
}

// ---------------- kernel: node update ----------------
__global__ void node_k(const float* __restrict__ n1w, const float* __restrict__ n1b,
                       const float* __restrict__ n2w, const float* __restrict__ n2b,
                       float* __restrict__ out_h) {
    int row = blockIdx.x, f = threadIdx.x;
    __shared__ float hln[F_], agg[F_], nu[F_];
    hln[f] = g_hln[row*F_ + f];
    agg[f] = g_agg[row*F_ + f];
    __syncthreads();
    float z = n1b[f];
    const float* wr = n1w + f*256;     // node1_w row: [h part | agg part]
    #pragma unroll 4
    for (int k = 0; k < F_; k++) z += wr[k]*hln[k] + wr[128 + k]*agg[k];
    nu[f] = siluf(z);
    __syncthreads();
    float o = n2b[f];
    const float* w2r = n2w + f*F_;
    #pragma unroll 4
    for (int k = 0; k < F_; k++) o += w2r[k]*nu[k];
    out_h[row*F_ + f] = hln[f] + o;
}

// ---------------- launch ----------------
extern "C" void kernel_launch(void* const* d_in, const int* in_sizes, int n_in,
                              void* d_out, int out_size) {
    const float* x      = (const float*)d_in[0];
    const float* h      = (const float*)d_in[1];
    const float* x0     = (const float*)d_in[2];
    const float* lnh_w  = (const float*)d_in[3];
    const float* lnh_b  = (const float*)d_in[4];
    const float* lnx_w  = (const float*)d_in[5];
    const float* lnx_b  = (const float*)d_in[6];
    const float* edg1_w = (const float*)d_in[7];
    const float* edg1_b = (const float*)d_in[8];
    const float* edg2_w = (const float*)d_in[9];
    const float* edg2_b = (const float*)d_in[10];
    const float* edgi_w = (const float*)d_in[11];
    const float* edgi_b = (const float*)d_in[12];
    const float* node1_w = (const float*)d_in[13];
    const float* node1_b = (const float*)d_in[14];
    const float* node2_w = (const float*)d_in[15];
    const float* node2_b = (const float*)d_in[16];
    const float* cor1_w = (const float*)d_in[17];
    const float* cor1_b = (const float*)d_in[18];
    const float* cor2_w = (const float*)d_in[19];
    const float* cor2_b = (const float*)d_in[20];
    const float* cor3_w = (const float*)d_in[21];
    const float* cor3_b = (const float*)d_in[22];

    float* out   = (float*)d_out;
    float* out_x = out;                 // (B,N,3) first
    float* out_h = out + BN_*3;         // then (B,N,F)

    cudaFuncSetAttribute(pair_k, cudaFuncAttributeMaxDynamicSharedMemorySize,
                         PAIR_SMEM_BYTES);

    transpose_k<<<F_, F_>>>(edg2_w, cor2_w);
    pre_k<<<BN_, F_>>>(x, h, lnh_w, lnh_b, lnx_w, lnx_b,
                       edg1_w, edg1_b, cor1_w, cor1_b);
    pair_k<<<BN_, 256, PAIR_SMEM_BYTES>>>(x, x0, edg1_w, cor1_w,
                                          edg2_b, cor2_b, edgi_w, edgi_b,
                                          cor3_w, cor3_b, out_x);
    node_k<<<BN_, F_>>>(node1_w, node1_b, node2_w, node2_b, out_h);
}

// round 6
// speedup vs baseline: 1.3740x; 1.3740x over previous
#include <cuda_runtime.h>

// Problem constants (B=4, N=256, F=128)
#define B_  4
#define N_  256
#define F_  128
#define BN_ (B_*N_)
#define TJ  64

// ---------------- device scratch (static: no allocation allowed) ----------------
__device__ float g_hln[BN_*F_];   // layernormed h
__device__ float g_xln[BN_*3];    // layernormed x
__device__ float g_Ae[BN_*F_];    // edg1_w[:, :F] @ h_ln + edg1_b
__device__ float g_Be[BN_*F_];    // edg1_w[:, F:2F] @ h_ln
__device__ float g_Ac[BN_*F_];    // cor1 analogues
__device__ float g_Bc[BN_*F_];
__device__ float g_agg[BN_*F_];   // sum_j e*m
__device__ float g_w2eT[F_*F_];   // edg2_w transposed (k-major)
__device__ float g_w2cT[F_*F_];   // cor2_w transposed
__device__ float g_n1wT[256*F_];  // node1_w transposed (k-major, k=0..255)
__device__ float g_n2wT[F_*F_];   // node2_w transposed
__device__ float g_e1T[256*F_];   // edg1_w[:, :2F] transposed
__device__ float g_c1T[256*F_];   // cor1_w[:, :2F] transposed

__device__ __forceinline__ float siluf(float z) { return z / (1.f + __expf(-z)); }

// ---- packed fp32x2 FMA (FFMA2; ptxas never emits it from C++) ----
__device__ __forceinline__ unsigned long long pack2(float x, float y) {
    unsigned long long r;
    asm("mov.b64 %0, {%1, %2};" : "=l"(r) : "f"(x), "f"(y));
    return r;
}
__device__ __forceinline__ void fma2(unsigned long long &d,
                                     unsigned long long a, unsigned long long b) {
    asm("fma.rn.f32x2 %0, %1, %2, %0;" : "+l"(d) : "l"(a), "l"(b));
}
__device__ __forceinline__ float2 unpack2(unsigned long long v) {
    float lo, hi;
    asm("mov.b64 {%0, %1}, %2;" : "=f"(lo), "=f"(hi) : "l"(v));
    return make_float2(lo, hi);
}

// ---------------- kernel: transpose weights to k-major ----------------
__global__ void transpose_k(const float* __restrict__ e2, const float* __restrict__ c2,
                            const float* __restrict__ n1, const float* __restrict__ n2,
                            const float* __restrict__ e1, const float* __restrict__ c1) {
    int k = blockIdx.x;   // 0..255
    int f = threadIdx.x;  // 0..127
    g_n1wT[k*F_ + f] = n1[f*256 + k];
    g_e1T [k*F_ + f] = e1[f*258 + k];
    g_c1T [k*F_ + f] = c1[f*258 + k];
    if (k < F_) {
        g_w2eT[k*F_ + f] = e2[f*F_ + k];
        g_w2cT[k*F_ + f] = c2[f*F_ + k];
        g_n2wT[k*F_ + f] = n2[f*F_ + k];
    }
}

// ---------------- kernel: per-node precompute (LN + layer-1 decomposition) ----------------
__global__ void pre_k(const float* __restrict__ x,  const float* __restrict__ h,
                      const float* __restrict__ lnh_w, const float* __restrict__ lnh_b,
                      const float* __restrict__ lnx_w, const float* __restrict__ lnx_b,
                      const float* __restrict__ e1b, const float* __restrict__ c1b) {
    int row = blockIdx.x;
    int f   = threadIdx.x;
    __shared__ float hln[F_];
    __shared__ float red[4];

    float v = h[row*F_ + f];
    float s = v;
    #pragma unroll
    for (int o = 16; o; o >>= 1) s += __shfl_xor_sync(0xffffffffu, s, o);
    int lane = f & 31, wp = f >> 5;
    if (lane == 0) red[wp] = s;
    __syncthreads();
    float mean = (red[0] + red[1] + red[2] + red[3]) * (1.f / F_);
    float d = v - mean;
    float s2 = d * d;
    #pragma unroll
    for (int o = 16; o; o >>= 1) s2 += __shfl_xor_sync(0xffffffffu, s2, o);
    __syncthreads();
    if (lane == 0) red[wp] = s2;
    __syncthreads();
    float var  = (red[0] + red[1] + red[2] + red[3]) * (1.f / F_);
    float rstd = rsqrtf(var + 1e-5f);
    float hl = d * rstd * lnh_w[f] + lnh_b[f];
    hln[f] = hl;
    g_hln[row*F_ + f] = hl;

    if (f == 0) {  // layernorm of x over 3 components
        float a0 = x[row*3+0], a1 = x[row*3+1], a2 = x[row*3+2];
        float m  = (a0 + a1 + a2) * (1.f/3.f);
        float d0 = a0 - m, d1 = a1 - m, d2 = a2 - m;
        float vr = (d0*d0 + d1*d1 + d2*d2) * (1.f/3.f);
        float rs = rsqrtf(vr + 1e-5f);
        g_xln[row*3+0] = d0*rs*lnx_w[0] + lnx_b[0];
        g_xln[row*3+1] = d1*rs*lnx_w[1] + lnx_b[1];
        g_xln[row*3+2] = d2*rs*lnx_w[2] + lnx_b[2];
    }
    __syncthreads();

    // A/B decomposition of layer-1 using k-major transposed weights (coalesced)
    float ae = e1b[f], be = 0.f, ac = c1b[f], bc = 0.f;
    #pragma unroll 4
    for (int k = 0; k < F_; k++) {
        float hk = hln[k];
        ae += g_e1T[k*F_ + f]        * hk;
        be += g_e1T[(128 + k)*F_ + f] * hk;
        ac += g_c1T[k*F_ + f]        * hk;
        bc += g_c1T[(128 + k)*F_ + f] * hk;
    }
    g_Ae[row*F_+f] = ae; g_Be[row*F_+f] = be;
    g_Ac[row*F_+f] = ac; g_Bc[row*F_+f] = bc;
}

// ---------------- the pair kernel: one CTA per (b,i) ----------------
// SMEM floats: w2e 16384 | w2c 16384 | m1e 8192 | m1c 8192 | dsq 64 | r0 64
//              shift 192 | xi 8 | aggred 1024 | csum 24   = 50528 floats = 202112 B
#define PAIR_SMEM_BYTES (50528 * 4)

__global__ __launch_bounds__(256, 1)
void pair_k(const float* __restrict__ x,   const float* __restrict__ x0,
            const float* __restrict__ e1w, const float* __restrict__ c1w,
            const float* __restrict__ e2b, const float* __restrict__ c2b,
            const float* __restrict__ eiw, const float* __restrict__ eib,
            const float* __restrict__ c3w, const float* __restrict__ c3b,
            float* __restrict__ out_x) {
    extern __shared__ float sm[];
    float* w2e      = sm;                  // [128][128] k-major
    float* w2c      = w2e + F_*F_;
    float* m1e      = w2c + F_*F_;         // [TJ][128]
    float* m1c      = m1e + TJ*F_;
    float* dsq_sh   = m1c + TJ*F_;         // [TJ]
    float* r0_sh    = dsq_sh + TJ;         // [TJ]
    float* shift_sh = r0_sh + TJ;          // [TJ][3]
    float* xi_sh    = shift_sh + TJ*3;     // x_i (3) at [0..2], x0_i (3) at [4..6]
    float* aggred   = xi_sh + 8;           // [8][128]
    float* csum_sh  = aggred + 8*F_;       // [8][3]

    int tid  = threadIdx.x;
    int rowI = blockIdx.x;
    int b    = rowI >> 8;
    int i    = rowI & 255;

    // stage both transposed weight matrices into SMEM (vectorized, conflict-free)
    for (int idx = tid; idx < F_*F_/4; idx += 256) {
        ((float4*)w2e)[idx] = ((const float4*)g_w2eT)[idx];
        ((float4*)w2c)[idx] = ((const float4*)g_w2cT)[idx];
    }
    if (tid < 3) {
        xi_sh[tid]     = x [rowI*3 + tid];
        xi_sh[4 + tid] = x0[rowI*3 + tid];
    }

    // per-feature constants for phase-1 (thread t handles f = t & 127)
    int f = tid & 127;
    float ae  = g_Ae[rowI*F_ + f];
    float ac  = g_Ac[rowI*F_ + f];
    float wed = e1w[f*258 + 256], wer = e1w[f*258 + 257];
    float wcd = c1w[f*258 + 256], wcr = c1w[f*258 + 257];

    // GEMM tiling: warp tj owns 8 j's, lane tf owns 4 f's (f = tf*4..tf*4+3)
    int tj = tid >> 5, tf = tid & 31;
    float4 b2e = ((const float4*)e2b)[tf];
    float4 b2c = ((const float4*)c2b)[tf];
    float4 wie = ((const float4*)eiw)[tf];
    float4 w3v = ((const float4*)c3w)[tf];
    float  bie = eib[0], b3 = c3b[0];

    float4 aggr = make_float4(0.f, 0.f, 0.f, 0.f);
    float  csum_acc = 0.f;

    __syncthreads();

    for (int j0 = 0; j0 < N_; j0 += TJ) {
        // ---- phase 0: per-j geometric scalars ----
        if (tid < TJ) {
            int j = j0 + tid;
            const float* xj = x + (b*N_ + j)*3;
            float dx = xi_sh[0] - xj[0];
            float dy = xi_sh[1] - xj[1];
            float dz = xi_sh[2] - xj[2];
            float ds = dx*dx + dy*dy + dz*dz;
            float r  = sqrtf(ds);
            float ri = 1.f / (r + 1.f);
            dsq_sh[tid] = ds;
            shift_sh[tid*3+0] = dx * ri;
            shift_sh[tid*3+1] = dy * ri;
            shift_sh[tid*3+2] = dz * ri;
            const float* x0j = x0 + (b*N_ + j)*3;
            float ex = xi_sh[4] - x0j[0];
            float ey = xi_sh[5] - x0j[1];
            float ez = xi_sh[6] - x0j[2];
            r0_sh[tid] = sqrtf(ex*ex + ey*ey + ez*ez);
        }
        __syncthreads();

        // ---- phase 1: layer-1 (decomposed) + silu -> m1 tiles ----
        {
            int jj0 = tid >> 7;   // threads 0..127 do even jj, 128..255 odd jj
            #pragma unroll 4
            for (int jj = jj0; jj < TJ; jj += 2) {
                int j = j0 + jj;
                float be = g_Be[(b*N_ + j)*F_ + f];
                float bc = g_Bc[(b*N_ + j)*F_ + f];
                float ds = dsq_sh[jj], rr = r0_sh[jj];
                float ze = ae + be + wed*ds + wer*rr;
                float zc = ac + bc + wcd*ds + wcr*rr;
                m1e[jj*F_ + f] = siluf(ze);
                m1c[jj*F_ + f] = siluf(zc);
            }
        }
        __syncthreads();

        // ---- phase 2a: edge GEMM (64x128 @ 128x128), 8j x 4f per thread, FFMA2 ----
        {
            unsigned long long acc0[8], acc1[8];
            #pragma unroll
            for (int jj = 0; jj < 8; jj++) {
                acc0[jj] = pack2(b2e.x, b2e.y);
                acc1[jj] = pack2(b2e.z, b2e.w);
            }
            for (int k = 0; k < F_; k += 4) {
                ulonglong2 wA = *(const ulonglong2*)&w2e[(k+0)*F_ + tf*4];
                ulonglong2 wB = *(const ulonglong2*)&w2e[(k+1)*F_ + tf*4];
                ulonglong2 wC = *(const ulonglong2*)&w2e[(k+2)*F_ + tf*4];
                ulonglong2 wD = *(const ulonglong2*)&w2e[(k+3)*F_ + tf*4];
                #pragma unroll
                for (int jj = 0; jj < 8; jj++) {
                    float4 av = *(const float4*)&m1e[(tj*8+jj)*F_ + k];
                    unsigned long long vx = pack2(av.x, av.x);
                    fma2(acc0[jj], vx, wA.x); fma2(acc1[jj], vx, wA.y);
                    unsigned long long vy = pack2(av.y, av.y);
                    fma2(acc0[jj], vy, wB.x); fma2(acc1[jj], vy, wB.y);
                    unsigned long long vz = pack2(av.z, av.z);
                    fma2(acc0[jj], vz, wC.x); fma2(acc1[jj], vz, wC.y);
                    unsigned long long vw = pack2(av.w, av.w);
                    fma2(acc0[jj], vw, wD.x); fma2(acc1[jj], vw, wD.y);
                }
            }
            #pragma unroll
            for (int jj = 0; jj < 8; jj++) {
                float2 p01 = unpack2(acc0[jj]);
                float2 p23 = unpack2(acc1[jj]);
                float m0 = siluf(p01.x);
                float m1 = siluf(p01.y);
                float m2 = siluf(p23.x);
                float m3 = siluf(p23.y);
                float p = m0*wie.x + m1*wie.y + m2*wie.z + m3*wie.w;
                #pragma unroll
                for (int o = 16; o; o >>= 1) p += __shfl_xor_sync(0xffffffffu, p, o);
                float e = 1.f / (1.f + __expf(-(p + bie)));
                int j = j0 + tj*8 + jj;
                if (j == i) e = 0.f;                      // (1 - eye) mask
                aggr.x += e*m0; aggr.y += e*m1; aggr.z += e*m2; aggr.w += e*m3;
            }
        }

        // ---- phase 2b: coordinate GEMM ----
        {
            unsigned long long acc0[8], acc1[8];
            #pragma unroll
            for (int jj = 0; jj < 8; jj++) {
                acc0[jj] = pack2(b2c.x, b2c.y);
                acc1[jj] = pack2(b2c.z, b2c.w);
            }
            for (int k = 0; k < F_; k += 4) {
                ulonglong2 wA = *(const ulonglong2*)&w2c[(k+0)*F_ + tf*4];
                ulonglong2 wB = *(const ulonglong2*)&w2c[(k+1)*F_ + tf*4];
                ulonglong2 wC = *(const ulonglong2*)&w2c[(k+2)*F_ + tf*4];
                ulonglong2 wD = *(const ulonglong2*)&w2c[(k+3)*F_ + tf*4];
                #pragma unroll
                for (int jj = 0; jj < 8; jj++) {
                    float4 av = *(const float4*)&m1c[(tj*8+jj)*F_ + k];
                    unsigned long long vx = pack2(av.x, av.x);
                    fma2(acc0[jj], vx, wA.x); fma2(acc1[jj], vx, wA.y);
                    unsigned long long vy = pack2(av.y, av.y);
                    fma2(acc0[jj], vy, wB.x); fma2(acc1[jj], vy, wB.y);
                    unsigned long long vz = pack2(av.z, av.z);
                    fma2(acc0[jj], vz, wC.x); fma2(acc1[jj], vz, wC.y);
                    unsigned long long vw = pack2(av.w, av.w);
                    fma2(acc0[jj], vw, wD.x); fma2(acc1[jj], vw, wD.y);
                }
            }
            #pragma unroll
            for (int jj = 0; jj < 8; jj++) {
                float2 p01 = unpack2(acc0[jj]);
                float2 p23 = unpack2(acc1[jj]);
                float m0 = siluf(p01.x);
                float m1 = siluf(p01.y);
                float m2 = siluf(p23.x);
                float m3 = siluf(p23.y);
                float p = m0*w3v.x + m1*w3v.y + m2*w3v.z + m3*w3v.w;
                #pragma unroll
                for (int o = 16; o; o >>= 1) p += __shfl_xor_sync(0xffffffffu, p, o);
                float cw = p + b3;                        // no activation on cor3
                float sv = (tf < 3) ? shift_sh[(tj*8+jj)*3 + tf] : 0.f;
                csum_acc += cw * sv;                      // diagonal: shift == 0 exactly
            }
        }
        __syncthreads();   // protect m1/scalars before next tile overwrites
    }

    // ---- final reductions across the 8 warps ----
    *((float4*)&aggred[tj*F_ + tf*4]) = aggr;
    if (tf < 3) csum_sh[tj*3 + tf] = csum_acc;
    __syncthreads();
    if (tid < F_) {
        float s = 0.f;
        #pragma unroll
        for (int w = 0; w < 8; w++) s += aggred[w*F_ + tid];
        g_agg[rowI*F_ + tid] = s;
    }
    if (tid < 3) {
        float s = 0.f;
        #pragma unroll
        for (int w = 0; w < 8; w++) s += csum_sh[w*3 + tid];
        out_x[rowI*3 + tid] = g_xln[rowI*3 + tid] + s;
    }
}

// ---------------- kernel: node update (k-major weights -> coalesced) ----------------
__global__ void node_k(const float* __restrict__ n1b, const float* __restrict__ n2b,
                       float* __restrict__ out_h) {
    int row = blockIdx.x, f = threadIdx.x;
    __shared__ float hln[F_], agg[F_], nu[F_];
    hln[f] = g_hln[row*F_ + f];
    agg[f] = g_agg[row*F_ + f];
    __syncthreads();
    float z = n1b[f];
    #pragma unroll 4
    for (int k = 0; k < F_; k++)
        z += g_n1wT[k*F_ + f]*hln[k] + g_n1wT[(128 + k)*F_ + f]*agg[k];
    nu[f] = siluf(z);
    __syncthreads();
    float o = n2b[f];
    #pragma unroll 4
    for (int k = 0; k < F_; k++) o += g_n2wT[k*F_ + f]*nu[k];
    out_h[row*F_ + f] = hln[f] + o;
}

// ---------------- launch ----------------
extern "C" void kernel_launch(void* const* d_in, const int* in_sizes, int n_in,
                              void* d_out, int out_size) {
    const float* x      = (const float*)d_in[0];
    const float* h      = (const float*)d_in[1];
    const float* x0     = (const float*)d_in[2];
    const float* lnh_w  = (const float*)d_in[3];
    const float* lnh_b  = (const float*)d_in[4];
    const float* lnx_w  = (const float*)d_in[5];
    const float* lnx_b  = (const float*)d_in[6];
    const float* edg1_w = (const float*)d_in[7];
    const float* edg1_b = (const float*)d_in[8];
    const float* edg2_w = (const float*)d_in[9];
    const float* edg2_b = (const float*)d_in[10];
    const float* edgi_w = (const float*)d_in[11];
    const float* edgi_b = (const float*)d_in[12];
    const float* node1_w = (const float*)d_in[13];
    const float* node1_b = (const float*)d_in[14];
    const float* node2_w = (const float*)d_in[15];
    const float* node2_b = (const float*)d_in[16];
    const float* cor1_w = (const float*)d_in[17];
    const float* cor1_b = (const float*)d_in[18];
    const float* cor2_w = (const float*)d_in[19];
    const float* cor2_b = (const float*)d_in[20];
    const float* cor3_w = (const float*)d_in[21];
    const float* cor3_b = (const float*)d_in[22];

    float* out   = (float*)d_out;
    float* out_x = out;                 // (B,N,3) first
    float* out_h = out + BN_*3;         // then (B,N,F)

    cudaFuncSetAttribute(pair_k, cudaFuncAttributeMaxDynamicSharedMemorySize,
                         PAIR_SMEM_BYTES);

    transpose_k<<<256, F_>>>(edg2_w, cor2_w, node1_w, node2_w, edg1_w, cor1_w);
    pre_k<<<BN_, F_>>>(x, h, lnh_w, lnh_b, lnx_w, lnx_b, edg1_b, cor1_b);
    pair_k<<<BN_, 256, PAIR_SMEM_BYTES>>>(x, x0, edg1_w, cor1_w,
                                          edg2_b, cor2_b, edgi_w, edgi_b,
                                          cor3_w, cor3_b, out_x);
    node_k<<<BN_, F_>>>(node1_b, node2_b, out_h);
}

// round 7
// speedup vs baseline: 1.3748x; 1.0006x over previous
#include <cuda_runtime.h>

// Problem constants (B=4, N=256, F=128)
#define B_  4
#define N_  256
#define F_  128
#define BN_ (B_*N_)
#define TJ  64

// ---------------- device scratch (static: no allocation allowed) ----------------
__device__ float g_hln[BN_*F_];   // layernormed h
__device__ float g_xln[BN_*3];    // layernormed x
__device__ float g_Ae[BN_*F_];    // edg1_w[:, :F] @ h_ln + edg1_b
__device__ float g_Be[BN_*F_];    // edg1_w[:, F:2F] @ h_ln
__device__ float g_Ac[BN_*F_];    // cor1 analogues
__device__ float g_Bc[BN_*F_];
__device__ float g_agg[BN_*F_];   // sum_j e*m
__device__ float g_w2eT[F_*F_];   // edg2_w transposed (k-major)
__device__ float g_w2cT[F_*F_];   // cor2_w transposed
__device__ float g_n1wT[256*F_];  // node1_w transposed (k-major, k=0..255)
__device__ float g_n2wT[F_*F_];   // node2_w transposed
__device__ float g_e1T[256*F_];   // edg1_w[:, :2F] transposed
__device__ float g_c1T[256*F_];   // cor1_w[:, :2F] transposed

__device__ __forceinline__ float siluf(float z) { return z / (1.f + __expf(-z)); }

// ---- packed fp32x2 FMA (FFMA2; ptxas never emits it from C++) ----
__device__ __forceinline__ unsigned long long pack2(float x, float y) {
    unsigned long long r;
    asm("mov.b64 %0, {%1, %2};" : "=l"(r) : "f"(x), "f"(y));
    return r;
}
__device__ __forceinline__ void fma2(unsigned long long &d,
                                     unsigned long long a, unsigned long long b) {
    asm("fma.rn.f32x2 %0, %1, %2, %0;" : "+l"(d) : "l"(a), "l"(b));
}
__device__ __forceinline__ float2 unpack2(unsigned long long v) {
    float lo, hi;
    asm("mov.b64 {%0, %1}, %2;" : "=f"(lo), "=f"(hi) : "l"(v));
    return make_float2(lo, hi);
}

// ---------------- kernel: transpose weights to k-major ----------------
__global__ void transpose_k(const float* __restrict__ e2, const float* __restrict__ c2,
                            const float* __restrict__ n1, const float* __restrict__ n2,
                            const float* __restrict__ e1, const float* __restrict__ c1) {
    int k = blockIdx.x;   // 0..255
    int f = threadIdx.x;  // 0..127
    g_n1wT[k*F_ + f] = n1[f*256 + k];
    g_e1T [k*F_ + f] = e1[f*258 + k];
    g_c1T [k*F_ + f] = c1[f*258 + k];
    if (k < F_) {
        g_w2eT[k*F_ + f] = e2[f*F_ + k];
        g_w2cT[k*F_ + f] = c2[f*F_ + k];
        g_n2wT[k*F_ + f] = n2[f*F_ + k];
    }
}

// ---------------- kernel: per-node precompute (LN + layer-1 decomposition) ----------------
__global__ void pre_k(const float* __restrict__ x,  const float* __restrict__ h,
                      const float* __restrict__ lnh_w, const float* __restrict__ lnh_b,
                      const float* __restrict__ lnx_w, const float* __restrict__ lnx_b,
                      const float* __restrict__ e1b, const float* __restrict__ c1b) {
    int row = blockIdx.x;
    int f   = threadIdx.x;
    __shared__ float hln[F_];
    __shared__ float red[4];

    float v = h[row*F_ + f];
    float s = v;
    #pragma unroll
    for (int o = 16; o; o >>= 1) s += __shfl_xor_sync(0xffffffffu, s, o);
    int lane = f & 31, wp = f >> 5;
    if (lane == 0) red[wp] = s;
    __syncthreads();
    float mean = (red[0] + red[1] + red[2] + red[3]) * (1.f / F_);
    float d = v - mean;
    float s2 = d * d;
    #pragma unroll
    for (int o = 16; o; o >>= 1) s2 += __shfl_xor_sync(0xffffffffu, s2, o);
    __syncthreads();
    if (lane == 0) red[wp] = s2;
    __syncthreads();
    float var  = (red[0] + red[1] + red[2] + red[3]) * (1.f / F_);
    float rstd = rsqrtf(var + 1e-5f);
    float hl = d * rstd * lnh_w[f] + lnh_b[f];
    hln[f] = hl;
    g_hln[row*F_ + f] = hl;

    if (f == 0) {  // layernorm of x over 3 components
        float a0 = x[row*3+0], a1 = x[row*3+1], a2 = x[row*3+2];
        float m  = (a0 + a1 + a2) * (1.f/3.f);
        float d0 = a0 - m, d1 = a1 - m, d2 = a2 - m;
        float vr = (d0*d0 + d1*d1 + d2*d2) * (1.f/3.f);
        float rs = rsqrtf(vr + 1e-5f);
        g_xln[row*3+0] = d0*rs*lnx_w[0] + lnx_b[0];
        g_xln[row*3+1] = d1*rs*lnx_w[1] + lnx_b[1];
        g_xln[row*3+2] = d2*rs*lnx_w[2] + lnx_b[2];
    }
    __syncthreads();

    // A/B decomposition of layer-1 using k-major transposed weights (coalesced)
    float ae = e1b[f], be = 0.f, ac = c1b[f], bc = 0.f;
    #pragma unroll 4
    for (int k = 0; k < F_; k++) {
        float hk = hln[k];
        ae += g_e1T[k*F_ + f]        * hk;
        be += g_e1T[(128 + k)*F_ + f] * hk;
        ac += g_c1T[k*F_ + f]        * hk;
        bc += g_c1T[(128 + k)*F_ + f] * hk;
    }
    g_Ae[row*F_+f] = ae; g_Be[row*F_+f] = be;
    g_Ac[row*F_+f] = ac; g_Bc[row*F_+f] = bc;
}

// ---------------- the pair kernel: one CTA per (b,i) ----------------
// SMEM floats: w2e 16384 | w2c 16384 | m1e 8192 | m1c 8192 | dsq 64 | r0 64
//              shift 192 | xi 8 | aggred 1024 | csum 24   = 50528 floats = 202112 B
#define PAIR_SMEM_BYTES (50528 * 4)

__global__ __launch_bounds__(256, 1)
void pair_k(const float* __restrict__ x,   const float* __restrict__ x0,
            const float* __restrict__ e1w, const float* __restrict__ c1w,
            const float* __restrict__ e2b, const float* __restrict__ c2b,
            const float* __restrict__ eiw, const float* __restrict__ eib,
            const float* __restrict__ c3w, const float* __restrict__ c3b,
            float* __restrict__ out_x) {
    extern __shared__ float sm[];
    float* w2e      = sm;                  // [128][128] k-major
    float* w2c      = w2e + F_*F_;
    float* m1e      = w2c + F_*F_;         // [TJ][128]
    float* m1c      = m1e + TJ*F_;
    float* dsq_sh   = m1c + TJ*F_;         // [TJ]
    float* r0_sh    = dsq_sh + TJ;         // [TJ]
    float* shift_sh = r0_sh + TJ;          // [TJ][3]
    float* xi_sh    = shift_sh + TJ*3;     // x_i (3) at [0..2], x0_i (3) at [4..6]
    float* aggred   = xi_sh + 8;           // [8][128]
    float* csum_sh  = aggred + 8*F_;       // [8][3]

    int tid  = threadIdx.x;
    int rowI = blockIdx.x;
    int b    = rowI >> 8;
    int i    = rowI & 255;

    // stage both transposed weight matrices into SMEM (vectorized, conflict-free)
    for (int idx = tid; idx < F_*F_/4; idx += 256) {
        ((float4*)w2e)[idx] = ((const float4*)g_w2eT)[idx];
        ((float4*)w2c)[idx] = ((const float4*)g_w2cT)[idx];
    }
    if (tid < 3) {
        xi_sh[tid]     = x [rowI*3 + tid];
        xi_sh[4 + tid] = x0[rowI*3 + tid];
    }

    // per-feature constants for phase-1 (thread t handles f = t & 127)
    int f = tid & 127;
    float ae  = g_Ae[rowI*F_ + f];
    float ac  = g_Ac[rowI*F_ + f];
    float wed = e1w[f*258 + 256], wer = e1w[f*258 + 257];
    float wcd = c1w[f*258 + 256], wcr = c1w[f*258 + 257];

    // GEMM tiling: warp tj owns 8 j's, lane tf owns 4 f's (f = tf*4..tf*4+3)
    int tj = tid >> 5, tf = tid & 31;
    float4 b2e = ((const float4*)e2b)[tf];
    float4 b2c = ((const float4*)c2b)[tf];
    float4 wie = ((const float4*)eiw)[tf];
    float4 w3v = ((const float4*)c3w)[tf];
    float  bie = eib[0], b3 = c3b[0];

    float4 aggr = make_float4(0.f, 0.f, 0.f, 0.f);
    float  csum_acc = 0.f;

    __syncthreads();

    for (int j0 = 0; j0 < N_; j0 += TJ) {
        // ---- phase 0: per-j geometric scalars ----
        if (tid < TJ) {
            int j = j0 + tid;
            const float* xj = x + (b*N_ + j)*3;
            float dx = xi_sh[0] - xj[0];
            float dy = xi_sh[1] - xj[1];
            float dz = xi_sh[2] - xj[2];
            float ds = dx*dx + dy*dy + dz*dz;
            float r  = sqrtf(ds);
            float ri = 1.f / (r + 1.f);
            dsq_sh[tid] = ds;
            shift_sh[tid*3+0] = dx * ri;
            shift_sh[tid*3+1] = dy * ri;
            shift_sh[tid*3+2] = dz * ri;
            const float* x0j = x0 + (b*N_ + j)*3;
            float ex = xi_sh[4] - x0j[0];
            float ey = xi_sh[5] - x0j[1];
            float ez = xi_sh[6] - x0j[2];
            r0_sh[tid] = sqrtf(ex*ex + ey*ey + ez*ez);
        }
        __syncthreads();

        // ---- phase 1: layer-1 (decomposed) + silu -> m1 tiles ----
        {
            int jj0 = tid >> 7;   // threads 0..127 do even jj, 128..255 odd jj
            #pragma unroll 4
            for (int jj = jj0; jj < TJ; jj += 2) {
                int j = j0 + jj;
                float be = g_Be[(b*N_ + j)*F_ + f];
                float bc = g_Bc[(b*N_ + j)*F_ + f];
                float ds = dsq_sh[jj], rr = r0_sh[jj];
                float ze = ae + be + wed*ds + wer*rr;
                float zc = ac + bc + wcd*ds + wcr*rr;
                m1e[jj*F_ + f] = siluf(ze);
                m1c[jj*F_ + f] = siluf(zc);
            }
        }
        __syncthreads();

        // ---- phase 2a: edge GEMM (64x128 @ 128x128), 8j x 4f per thread, FFMA2 ----
        {
            unsigned long long acc0[8], acc1[8];
            #pragma unroll
            for (int jj = 0; jj < 8; jj++) {
                acc0[jj] = pack2(b2e.x, b2e.y);
                acc1[jj] = pack2(b2e.z, b2e.w);
            }
            for (int k = 0; k < F_; k += 4) {
                ulonglong2 wA = *(const ulonglong2*)&w2e[(k+0)*F_ + tf*4];
                ulonglong2 wB = *(const ulonglong2*)&w2e[(k+1)*F_ + tf*4];
                ulonglong2 wC = *(const ulonglong2*)&w2e[(k+2)*F_ + tf*4];
                ulonglong2 wD = *(const ulonglong2*)&w2e[(k+3)*F_ + tf*4];
                #pragma unroll
                for (int jj = 0; jj < 8; jj++) {
                    float4 av = *(const float4*)&m1e[(tj*8+jj)*F_ + k];
                    unsigned long long vx = pack2(av.x, av.x);
                    fma2(acc0[jj], vx, wA.x); fma2(acc1[jj], vx, wA.y);
                    unsigned long long vy = pack2(av.y, av.y);
                    fma2(acc0[jj], vy, wB.x); fma2(acc1[jj], vy, wB.y);
                    unsigned long long vz = pack2(av.z, av.z);
                    fma2(acc0[jj], vz, wC.x); fma2(acc1[jj], vz, wC.y);
                    unsigned long long vw = pack2(av.w, av.w);
                    fma2(acc0[jj], vw, wD.x); fma2(acc1[jj], vw, wD.y);
                }
            }
            #pragma unroll
            for (int jj = 0; jj < 8; jj++) {
                float2 p01 = unpack2(acc0[jj]);
                float2 p23 = unpack2(acc1[jj]);
                float m0 = siluf(p01.x);
                float m1 = siluf(p01.y);
                float m2 = siluf(p23.x);
                float m3 = siluf(p23.y);
                float p = m0*wie.x + m1*wie.y + m2*wie.z + m3*wie.w;
                #pragma unroll
                for (int o = 16; o; o >>= 1) p += __shfl_xor_sync(0xffffffffu, p, o);
                float e = 1.f / (1.f + __expf(-(p + bie)));
                int j = j0 + tj*8 + jj;
                if (j == i) e = 0.f;                      // (1 - eye) mask
                aggr.x += e*m0; aggr.y += e*m1; aggr.z += e*m2; aggr.w += e*m3;
            }
        }

        // ---- phase 2b: coordinate GEMM ----
        {
            unsigned long long acc0[8], acc1[8];
            #pragma unroll
            for (int jj = 0; jj < 8; jj++) {
                acc0[jj] = pack2(b2c.x, b2c.y);
                acc1[jj] = pack2(b2c.z, b2c.w);
            }
            for (int k = 0; k < F_; k += 4) {
                ulonglong2 wA = *(const ulonglong2*)&w2c[(k+0)*F_ + tf*4];
                ulonglong2 wB = *(const ulonglong2*)&w2c[(k+1)*F_ + tf*4];
                ulonglong2 wC = *(const ulonglong2*)&w2c[(k+2)*F_ + tf*4];
                ulonglong2 wD = *(const ulonglong2*)&w2c[(k+3)*F_ + tf*4];
                #pragma unroll
                for (int jj = 0; jj < 8; jj++) {
                    float4 av = *(const float4*)&m1c[(tj*8+jj)*F_ + k];
                    unsigned long long vx = pack2(av.x, av.x);
                    fma2(acc0[jj], vx, wA.x); fma2(acc1[jj], vx, wA.y);
                    unsigned long long vy = pack2(av.y, av.y);
                    fma2(acc0[jj], vy, wB.x); fma2(acc1[jj], vy, wB.y);
                    unsigned long long vz = pack2(av.z, av.z);
                    fma2(acc0[jj], vz, wC.x); fma2(acc1[jj], vz, wC.y);
                    unsigned long long vw = pack2(av.w, av.w);
                    fma2(acc0[jj], vw, wD.x); fma2(acc1[jj], vw, wD.y);
                }
            }
            #pragma unroll
            for (int jj = 0; jj < 8; jj++) {
                float2 p01 = unpack2(acc0[jj]);
                float2 p23 = unpack2(acc1[jj]);
                float m0 = siluf(p01.x);
                float m1 = siluf(p01.y);
                float m2 = siluf(p23.x);
                float m3 = siluf(p23.y);
                float p = m0*w3v.x + m1*w3v.y + m2*w3v.z + m3*w3v.w;
                #pragma unroll
                for (int o = 16; o; o >>= 1) p += __shfl_xor_sync(0xffffffffu, p, o);
                float cw = p + b3;                        // no activation on cor3
                float sv = (tf < 3) ? shift_sh[(tj*8+jj)*3 + tf] : 0.f;
                csum_acc += cw * sv;                      // diagonal: shift == 0 exactly
            }
        }
        __syncthreads();   // protect m1/scalars before next tile overwrites
    }

    // ---- final reductions across the 8 warps ----
    *((float4*)&aggred[tj*F_ + tf*4]) = aggr;
    if (tf < 3) csum_sh[tj*3 + tf] = csum_acc;
    __syncthreads();
    if (tid < F_) {
        float s = 0.f;
        #pragma unroll
        for (int w = 0; w < 8; w++) s += aggred[w*F_ + tid];
        g_agg[rowI*F_ + tid] = s;
    }
    if (tid < 3) {
        float s = 0.f;
        #pragma unroll
        for (int w = 0; w < 8; w++) s += csum_sh[w*3 + tid];
        out_x[rowI*3 + tid] = g_xln[rowI*3 + tid] + s;
    }
}

// ---------------- kernel: node update (k-major weights -> coalesced) ----------------
__global__ void node_k(const float* __restrict__ n1b, const float* __restrict__ n2b,
                       float* __restrict__ out_h) {
    int row = blockIdx.x, f = threadIdx.x;
    __shared__ float hln[F_], agg[F_], nu[F_];
    hln[f] = g_hln[row*F_ + f];
    agg[f] = g_agg[row*F_ + f];
    __syncthreads();
    float z = n1b[f];
    #pragma unroll 4
    for (int k = 0; k < F_; k++)
        z += g_n1wT[k*F_ + f]*hln[k] + g_n1wT[(128 + k)*F_ + f]*agg[k];
    nu[f] = siluf(z);
    __syncthreads();
    float o = n2b[f];
    #pragma unroll 4
    for (int k = 0; k < F_; k++) o += g_n2wT[k*F_ + f]*nu[k];
    out_h[row*F_ + f] = hln[f] + o;
}

// ---------------- launch ----------------
extern "C" void kernel_launch(void* const* d_in, const int* in_sizes, int n_in,
                              void* d_out, int out_size) {
    const float* x      = (const float*)d_in[0];
    const float* h      = (const float*)d_in[1];
    const float* x0     = (const float*)d_in[2];
    const float* lnh_w  = (const float*)d_in[3];
    const float* lnh_b  = (const float*)d_in[4];
    const float* lnx_w  = (const float*)d_in[5];
    const float* lnx_b  = (const float*)d_in[6];
    const float* edg1_w = (const float*)d_in[7];
    const float* edg1_b = (const float*)d_in[8];
    const float* edg2_w = (const float*)d_in[9];
    const float* edg2_b = (const float*)d_in[10];
    const float* edgi_w = (const float*)d_in[11];
    const float* edgi_b = (const float*)d_in[12];
    const float* node1_w = (const float*)d_in[13];
    const float* node1_b = (const float*)d_in[14];
    const float* node2_w = (const float*)d_in[15];
    const float* node2_b = (const float*)d_in[16];
    const float* cor1_w = (const float*)d_in[17];
    const float* cor1_b = (const float*)d_in[18];
    const float* cor2_w = (const float*)d_in[19];
    const float* cor2_b = (const float*)d_in[20];
    const float* cor3_w = (const float*)d_in[21];
    const float* cor3_b = (const float*)d_in[22];

    float* out   = (float*)d_out;
    float* out_x = out;                 // (B,N,3) first
    float* out_h = out + BN_*3;         // then (B,N,F)

    cudaFuncSetAttribute(pair_k, cudaFuncAttributeMaxDynamicSharedMemorySize,
                         PAIR_SMEM_BYTES);

    transpose_k<<<256, F_>>>(edg2_w, cor2_w, node1_w, node2_w, edg1_w, cor1_w);
    pre_k<<<BN_, F_>>>(x, h, lnh_w, lnh_b, lnx_w, lnx_b, edg1_b, cor1_b);
    pair_k<<<BN_, 256, PAIR_SMEM_BYTES>>>(x, x0, edg1_w, cor1_w,
                                          edg2_b, cor2_b, edgi_w, edgi_b,
                                          cor3_w, cor3_b, out_x);
    node_k<<<BN_, F_>>>(node1_b, node2_b, out_h);
}

// round 8
// speedup vs baseline: 1.8979x; 1.3805x over previous
#include <cuda_runtime.h>

// Problem constants (B=4, N=256, F=128)
#define B_  4
#define N_  256
#define F_  128
#define BN_ (B_*N_)
#define TJ  64
#define MS  68        // m1T row stride (floats): 68 % 32 == 4 -> conflict-free stores, 16B aligned
#define RB  8         // rows per CTA in pre_k / node_k

// ---------------- device scratch (static: no allocation allowed) ----------------
__device__ float g_hln[BN_*F_];   // layernormed h
__device__ float g_xln[BN_*3];    // layernormed x
__device__ float g_Ae[BN_*F_];    // edg1_w[:, :F] @ h_ln + edg1_b
__device__ float g_Be[BN_*F_];    // edg1_w[:, F:2F] @ h_ln
__device__ float g_Ac[BN_*F_];    // cor1 analogues
__device__ float g_Bc[BN_*F_];
__device__ float g_agg[BN_*F_];   // sum_j e*m
__device__ float g_w2eT[F_*F_];   // edg2_w transposed (k-major)
__device__ float g_w2cT[F_*F_];   // cor2_w transposed
__device__ float g_n1wT[256*F_];  // node1_w transposed (k-major, k=0..255)
__device__ float g_n2wT[F_*F_];   // node2_w transposed
__device__ float g_e1T[256*F_];   // edg1_w[:, :2F] transposed
__device__ float g_c1T[256*F_];   // cor1_w[:, :2F] transposed

__device__ __forceinline__ float siluf(float z) { return z / (1.f + __expf(-z)); }

// ---- packed fp32x2 FMA (FFMA2; ptxas never emits it from C++) ----
__device__ __forceinline__ unsigned long long pack2(float x, float y) {
    unsigned long long r;
    asm("mov.b64 %0, {%1, %2};" : "=l"(r) : "f"(x), "f"(y));
    return r;
}
__device__ __forceinline__ void fma2(unsigned long long &d,
                                     unsigned long long a, unsigned long long b) {
    asm("fma.rn.f32x2 %0, %1, %2, %0;" : "+l"(d) : "l"(a), "l"(b));
}
__device__ __forceinline__ float2 unpack2(unsigned long long v) {
    float lo, hi;
    asm("mov.b64 {%0, %1}, %2;" : "=f"(lo), "=f"(hi) : "l"(v));
    return make_float2(lo, hi);
}

// ---------------- kernel: transpose weights to k-major ----------------
__global__ void transpose_k(const float* __restrict__ e2, const float* __restrict__ c2,
                            const float* __restrict__ n1, const float* __restrict__ n2,
                            const float* __restrict__ e1, const float* __restrict__ c1) {
    int k = blockIdx.x;   // 0..255
    int f = threadIdx.x;  // 0..127
    g_n1wT[k*F_ + f] = n1[f*256 + k];
    g_e1T [k*F_ + f] = e1[f*258 + k];
    g_c1T [k*F_ + f] = c1[f*258 + k];
    if (k < F_) {
        g_w2eT[k*F_ + f] = e2[f*F_ + k];
        g_w2cT[k*F_ + f] = c2[f*F_ + k];
        g_n2wT[k*F_ + f] = n2[f*F_ + k];
    }
}

// ---------------- kernel: per-node precompute, 8 rows per CTA ----------------
__global__ void pre_k(const float* __restrict__ x,  const float* __restrict__ h,
                      const float* __restrict__ lnh_w, const float* __restrict__ lnh_b,
                      const float* __restrict__ lnx_w, const float* __restrict__ lnx_b,
                      const float* __restrict__ e1b, const float* __restrict__ c1b) {
    int row0 = blockIdx.x * RB;
    int f    = threadIdx.x;
    int lane = f & 31, wp = f >> 5;
    __shared__ float hln[RB][F_];
    __shared__ float red[RB][4];

    float v[RB], d[RB];
    #pragma unroll
    for (int r = 0; r < RB; r++) v[r] = h[(row0 + r)*F_ + f];
    #pragma unroll
    for (int r = 0; r < RB; r++) {
        float s = v[r];
        #pragma unroll
        for (int o = 16; o; o >>= 1) s += __shfl_xor_sync(0xffffffffu, s, o);
        if (lane == 0) red[r][wp] = s;
    }
    __syncthreads();
    #pragma unroll
    for (int r = 0; r < RB; r++) {
        float mean = (red[r][0] + red[r][1] + red[r][2] + red[r][3]) * (1.f / F_);
        d[r] = v[r] - mean;
    }
    __syncthreads();
    #pragma unroll
    for (int r = 0; r < RB; r++) {
        float s2 = d[r] * d[r];
        #pragma unroll
        for (int o = 16; o; o >>= 1) s2 += __shfl_xor_sync(0xffffffffu, s2, o);
        if (lane == 0) red[r][wp] = s2;
    }
    __syncthreads();
    float gw = lnh_w[f], gb = lnh_b[f];
    #pragma unroll
    for (int r = 0; r < RB; r++) {
        float var  = (red[r][0] + red[r][1] + red[r][2] + red[r][3]) * (1.f / F_);
        float hl = d[r] * rsqrtf(var + 1e-5f) * gw + gb;
        hln[r][f] = hl;
        g_hln[(row0 + r)*F_ + f] = hl;
    }

    if (f < RB) {  // layernorm of x (3 comps) for row f
        int row = row0 + f;
        float a0 = x[row*3+0], a1 = x[row*3+1], a2 = x[row*3+2];
        float m  = (a0 + a1 + a2) * (1.f/3.f);
        float d0 = a0 - m, d1 = a1 - m, d2 = a2 - m;
        float vr = (d0*d0 + d1*d1 + d2*d2) * (1.f/3.f);
        float rs = rsqrtf(vr + 1e-5f);
        g_xln[row*3+0] = d0*rs*lnx_w[0] + lnx_b[0];
        g_xln[row*3+1] = d1*rs*lnx_w[1] + lnx_b[1];
        g_xln[row*3+2] = d2*rs*lnx_w[2] + lnx_b[2];
    }
    __syncthreads();

    // A/B decomposition of layer-1: 4 weight loads feed 32 FMAs (8 rows)
    float ae[RB], be[RB], ac[RB], bc[RB];
    float eb = e1b[f], cb = c1b[f];
    #pragma unroll
    for (int r = 0; r < RB; r++) { ae[r] = eb; be[r] = 0.f; ac[r] = cb; bc[r] = 0.f; }
    #pragma unroll 2
    for (int k = 0; k < F_; k++) {
        float ea = g_e1T[k*F_ + f];
        float eB = g_e1T[(128 + k)*F_ + f];
        float ca = g_c1T[k*F_ + f];
        float cB = g_c1T[(128 + k)*F_ + f];
        #pragma unroll
        for (int r = 0; r < RB; r++) {
            float hk = hln[r][k];
            ae[r] += ea*hk; be[r] += eB*hk; ac[r] += ca*hk; bc[r] += cB*hk;
        }
    }
    #pragma unroll
    for (int r = 0; r < RB; r++) {
        g_Ae[(row0+r)*F_+f] = ae[r]; g_Be[(row0+r)*F_+f] = be[r];
        g_Ac[(row0+r)*F_+f] = ac[r]; g_Bc[(row0+r)*F_+f] = bc[r];
    }
}

// ---------------- the pair kernel: one CTA per (b,i), 512 threads ----------------
// SMEM floats: w2e 16384 | w2c 16384 | m1eT 128*68 | m1cT 128*68 | dsq 64 | r0 64
//              shift 192 | xi 8 | aggred 8*128 | csum 8*4  = 51560 floats = 206240 B
#define PAIR_SMEM_BYTES (51560 * 4)

__global__ __launch_bounds__(512, 1)
void pair_k(const float* __restrict__ x,   const float* __restrict__ x0,
            const float* __restrict__ e1w, const float* __restrict__ c1w,
            const float* __restrict__ e2b, const float* __restrict__ c2b,
            const float* __restrict__ eiw, const float* __restrict__ eib,
            const float* __restrict__ c3w, const float* __restrict__ c3b,
            float* __restrict__ out_x) {
    extern __shared__ float sm[];
    float* w2e      = sm;                  // [128][128] k-major
    float* w2c      = w2e + F_*F_;
    float* m1eT     = w2c + F_*F_;         // [128 k][68] (j in columns)
    float* m1cT     = m1eT + F_*MS;
    float* dsq_sh   = m1cT + F_*MS;        // [TJ]
    float* r0_sh    = dsq_sh + TJ;         // [TJ]
    float* shift_sh = r0_sh + TJ;          // [TJ][3]
    float* xi_sh    = shift_sh + TJ*3;     // x_i (3) at [0..2], x0_i (3) at [4..6]
    float* aggred   = xi_sh + 8;           // [8][128]
    float* csum_sh  = aggred + 8*F_;       // [8][4]

    int tid  = threadIdx.x;
    int rowI = blockIdx.x;
    int b    = rowI >> 8;
    int i    = rowI & 255;

    // stage both transposed weight matrices into SMEM
    for (int idx = tid; idx < F_*F_/4; idx += 512) {
        ((float4*)w2e)[idx] = ((const float4*)g_w2eT)[idx];
        ((float4*)w2c)[idx] = ((const float4*)g_w2cT)[idx];
    }
    if (tid < 3) {
        xi_sh[tid]     = x [rowI*3 + tid];
        xi_sh[4 + tid] = x0[rowI*3 + tid];
    }

    // phase-1 mapping: thread handles feature f1, j's congruent to jg (mod 4)
    int f1 = tid >> 2;
    int jg = tid & 3;
    float ae  = g_Ae[rowI*F_ + f1];
    float ac  = g_Ac[rowI*F_ + f1];
    float wed = e1w[f1*258 + 256], wer = e1w[f1*258 + 257];
    float wcd = c1w[f1*258 + 256], wcr = c1w[f1*258 + 257];

    // GEMM mapping: 16 warps; wg = role (0 edge, 1 cor); wj = j-octet; lane tf = f quad
    int w  = tid >> 5, tf = tid & 31;
    int wg = w >> 3, wj = w & 7;
    const float* w2  = wg ? w2c : w2e;
    const float* m1T = wg ? m1cT : m1eT;
    float4 b2   = ((const float4*)(wg ? c2b : e2b))[tf];
    float4 wout = ((const float4*)(wg ? c3w : eiw))[tf];
    float  bout = wg ? c3b[0] : eib[0];

    float4 aggr = make_float4(0.f, 0.f, 0.f, 0.f);   // edge warps only
    float  csum_acc = 0.f;                            // cor warps only

    __syncthreads();

    for (int j0 = 0; j0 < N_; j0 += TJ) {
        // ---- phase 0: per-j geometric scalars ----
        if (tid < TJ) {
            int j = j0 + tid;
            const float* xj = x + (b*N_ + j)*3;
            float dx = xi_sh[0] - xj[0];
            float dy = xi_sh[1] - xj[1];
            float dz = xi_sh[2] - xj[2];
            float ds = dx*dx + dy*dy + dz*dz;
            float r  = sqrtf(ds);
            float ri = 1.f / (r + 1.f);
            dsq_sh[tid] = ds;
            shift_sh[tid*3+0] = dx * ri;
            shift_sh[tid*3+1] = dy * ri;
            shift_sh[tid*3+2] = dz * ri;
            const float* x0j = x0 + (b*N_ + j)*3;
            float ex = xi_sh[4] - x0j[0];
            float ey = xi_sh[5] - x0j[1];
            float ez = xi_sh[6] - x0j[2];
            r0_sh[tid] = sqrtf(ex*ex + ey*ey + ez*ez);
        }
        __syncthreads();

        // ---- phase 1: layer-1 (decomposed) + silu -> transposed m1 tiles ----
        #pragma unroll
        for (int jj = jg; jj < TJ; jj += 4) {
            int j = j0 + jj;
            float be = g_Be[(b*N_ + j)*F_ + f1];
            float bc = g_Bc[(b*N_ + j)*F_ + f1];
            float ds = dsq_sh[jj], rr = r0_sh[jj];
            float ze = ae + be + wed*ds + wer*rr;
            float zc = ac + bc + wcd*ds + wcr*rr;
            m1eT[f1*MS + jj] = siluf(ze);
            m1cT[f1*MS + jj] = siluf(zc);
        }
        __syncthreads();

        // ---- phase 2: role-split GEMM (each warp: 8 j x 128 f, lane: 8 j x 4 f) ----
        {
            unsigned long long acc[4][4];   // [j-pair][f]
            #pragma unroll
            for (int p = 0; p < 4; p++) {
                acc[p][0] = pack2(b2.x, b2.x);
                acc[p][1] = pack2(b2.y, b2.y);
                acc[p][2] = pack2(b2.z, b2.z);
                acc[p][3] = pack2(b2.w, b2.w);
            }
            #pragma unroll 4
            for (int k = 0; k < F_; k++) {
                float4 w4 = *(const float4*)&w2[k*F_ + tf*4];
                ulonglong2 mA = *(const ulonglong2*)&m1T[k*MS + wj*8];      // (j0,j1),(j2,j3)
                ulonglong2 mB = *(const ulonglong2*)&m1T[k*MS + wj*8 + 4];  // (j4,j5),(j6,j7)
                unsigned long long ws;
                ws = pack2(w4.x, w4.x);
                fma2(acc[0][0], mA.x, ws); fma2(acc[1][0], mA.y, ws);
                fma2(acc[2][0], mB.x, ws); fma2(acc[3][0], mB.y, ws);
                ws = pack2(w4.y, w4.y);
                fma2(acc[0][1], mA.x, ws); fma2(acc[1][1], mA.y, ws);
                fma2(acc[2][1], mB.x, ws); fma2(acc[3][1], mB.y, ws);
                ws = pack2(w4.z, w4.z);
                fma2(acc[0][2], mA.x, ws); fma2(acc[1][2], mA.y, ws);
                fma2(acc[2][2], mB.x, ws); fma2(acc[3][2], mB.y, ws);
                ws = pack2(w4.w, w4.w);
                fma2(acc[0][3], mA.x, ws); fma2(acc[1][3], mA.y, ws);
                fma2(acc[2][3], mB.x, ws); fma2(acc[3][3], mB.y, ws);
            }
            // epilogue: per j, silu -> 1-wide head -> gate/accumulate
            #pragma unroll
            for (int p = 0; p < 4; p++) {
                float2 h0 = unpack2(acc[p][0]);
                float2 h1 = unpack2(acc[p][1]);
                float2 h2 = unpack2(acc[p][2]);
                float2 h3 = unpack2(acc[p][3]);
                #pragma unroll
                for (int q = 0; q < 2; q++) {
                    int jj = wj*8 + p*2 + q;
                    float m0 = siluf(q ? h0.y : h0.x);
                    float m1 = siluf(q ? h1.y : h1.x);
                    float m2 = siluf(q ? h2.y : h2.x);
                    float m3 = siluf(q ? h3.y : h3.x);
                    float pdot = m0*wout.x + m1*wout.y + m2*wout.z + m3*wout.w;
                    #pragma unroll
                    for (int o = 16; o; o >>= 1)
                        pdot += __shfl_xor_sync(0xffffffffu, pdot, o);
                    if (wg == 0) {
                        float e = 1.f / (1.f + __expf(-(pdot + bout)));
                        if (j0 + jj == i) e = 0.f;          // (1 - eye) mask
                        aggr.x += e*m0; aggr.y += e*m1; aggr.z += e*m2; aggr.w += e*m3;
                    } else {
                        float cw = pdot + bout;              // no activation on cor3
                        float sv = (tf < 3) ? shift_sh[jj*3 + tf] : 0.f;
                        csum_acc += cw * sv;                 // diagonal: shift == 0 exactly
                    }
                }
            }
        }
        __syncthreads();   // protect m1/scalars before next tile overwrites
    }

    // ---- final reductions across warps ----
    if (wg == 0) *((float4*)&aggred[wj*F_ + tf*4]) = aggr;
    else if (tf < 3) csum_sh[wj*4 + tf] = csum_acc;
    __syncthreads();
    if (tid < F_) {
        float s = 0.f;
        #pragma unroll
        for (int ww = 0; ww < 8; ww++) s += aggred[ww*F_ + tid];
        g_agg[rowI*F_ + tid] = s;
    }
    if (tid < 3) {
        float s = 0.f;
        #pragma unroll
        for (int ww = 0; ww < 8; ww++) s += csum_sh[ww*4 + tid];
        out_x[rowI*3 + tid] = g_xln[rowI*3 + tid] + s;
    }
}

// ---------------- kernel: node update, 8 rows per CTA ----------------
__global__ void node_k(const float* __restrict__ n1b, const float* __restrict__ n2b,
                       float* __restrict__ out_h) {
    int row0 = blockIdx.x * RB;
    int f    = threadIdx.x;
    __shared__ float hln[RB][F_], agg[RB][F_], nu[RB][F_];
    #pragma unroll
    for (int r = 0; r < RB; r++) {
        hln[r][f] = g_hln[(row0+r)*F_ + f];
        agg[r][f] = g_agg[(row0+r)*F_ + f];
    }
    __syncthreads();
    float z[RB];
    float b1 = n1b[f];
    #pragma unroll
    for (int r = 0; r < RB; r++) z[r] = b1;
    #pragma unroll 2
    for (int k = 0; k < F_; k++) {
        float w1 = g_n1wT[k*F_ + f];
        float w2 = g_n1wT[(128 + k)*F_ + f];
        #pragma unroll
        for (int r = 0; r < RB; r++) z[r] += w1*hln[r][k] + w2*agg[r][k];
    }
    #pragma unroll
    for (int r = 0; r < RB; r++) nu[r][f] = siluf(z[r]);
    __syncthreads();
    float o[RB];
    float b2 = n2b[f];
    #pragma unroll
    for (int r = 0; r < RB; r++) o[r] = b2;
    #pragma unroll 2
    for (int k = 0; k < F_; k++) {
        float wv = g_n2wT[k*F_ + f];
        #pragma unroll
        for (int r = 0; r < RB; r++) o[r] += wv*nu[r][k];
    }
    #pragma unroll
    for (int r = 0; r < RB; r++) out_h[(row0+r)*F_ + f] = hln[r][f] + o[r];
}

// ---------------- launch ----------------
extern "C" void kernel_launch(void* const* d_in, const int* in_sizes, int n_in,
                              void* d_out, int out_size) {
    const float* x      = (const float*)d_in[0];
    const float* h      = (const float*)d_in[1];
    const float* x0     = (const float*)d_in[2];
    const float* lnh_w  = (const float*)d_in[3];
    const float* lnh_b  = (const float*)d_in[4];
    const float* lnx_w  = (const float*)d_in[5];
    const float* lnx_b  = (const float*)d_in[6];
    const float* edg1_w = (const float*)d_in[7];
    const float* edg1_b = (const float*)d_in[8];
    const float* edg2_w = (const float*)d_in[9];
    const float* edg2_b = (const float*)d_in[10];
    const float* edgi_w = (const float*)d_in[11];
    const float* edgi_b = (const float*)d_in[12];
    const float* node1_w = (const float*)d_in[13];
    const float* node1_b = (const float*)d_in[14];
    const float* node2_w = (const float*)d_in[15];
    const float* node2_b = (const float*)d_in[16];
    const float* cor1_w = (const float*)d_in[17];
    const float* cor1_b = (const float*)d_in[18];
    const float* cor2_w = (const float*)d_in[19];
    const float* cor2_b = (const float*)d_in[20];
    const float* cor3_w = (const float*)d_in[21];
    const float* cor3_b = (const float*)d_in[22];

    float* out   = (float*)d_out;
    float* out_x = out;                 // (B,N,3) first
    float* out_h = out + BN_*3;         // then (B,N,F)

    cudaFuncSetAttribute(pair_k, cudaFuncAttributeMaxDynamicSharedMemorySize,
                         PAIR_SMEM_BYTES);

    transpose_k<<<256, F_>>>(edg2_w, cor2_w, node1_w, node2_w, edg1_w, cor1_w);
    pre_k<<<BN_/RB, F_>>>(x, h, lnh_w, lnh_b, lnx_w, lnx_b, edg1_b, cor1_b);
    pair_k<<<BN_, 512, PAIR_SMEM_BYTES>>>(x, x0, edg1_w, cor1_w,
                                          edg2_b, cor2_b, edgi_w, edgi_b,
                                          cor3_w, cor3_b, out_x);
    node_k<<<BN_/RB, F_>>>(node1_b, node2_b, out_h);
}

// round 9
// speedup vs baseline: 2.3352x; 1.2305x over previous
#include <cuda_runtime.h>

// Problem constants (B=4, N=256, F=128)
#define B_  4
#define N_  256
#define F_  128
#define BN_ (B_*N_)
#define TJ  64
#define MS  68        // m1T row stride (floats): stores land conflict-free, 16B aligned
#define RB  2         // rows per CTA in pre_k / node_k (512 CTAs -> good occupancy)

// ---------------- device scratch (static: no allocation allowed) ----------------
__device__ float g_hln[BN_*F_];   // layernormed h
__device__ float g_xln[BN_*3];    // layernormed x
__device__ float g_Ae[BN_*F_];    // edg1_w[:, :F] @ h_ln + edg1_b
__device__ float g_Be[BN_*F_];    // edg1_w[:, F:2F] @ h_ln
__device__ float g_Ac[BN_*F_];    // cor1 analogues
__device__ float g_Bc[BN_*F_];
__device__ float g_agg[BN_*F_];   // sum_j e*m
__device__ float g_w2eT[F_*F_];   // edg2_w transposed (k-major)
__device__ float g_w2cT[F_*F_];   // cor2_w transposed
__device__ float g_n1wT[256*F_];  // node1_w transposed (k-major, k=0..255)
__device__ float g_n2wT[F_*F_];   // node2_w transposed
__device__ float g_e1T[256*F_];   // edg1_w[:, :2F] transposed
__device__ float g_c1T[256*F_];   // cor1_w[:, :2F] transposed

__device__ __forceinline__ float siluf(float z) {
    return __fdividef(z, 1.f + __expf(-z));
}

// ---- packed fp32x2 FMA (FFMA2; ptxas never emits it from C++) ----
__device__ __forceinline__ unsigned long long pack2(float x, float y) {
    unsigned long long r;
    asm("mov.b64 %0, {%1, %2};" : "=l"(r) : "f"(x), "f"(y));
    return r;
}
__device__ __forceinline__ void fma2(unsigned long long &d,
                                     unsigned long long a, unsigned long long b) {
    asm("fma.rn.f32x2 %0, %1, %2, %0;" : "+l"(d) : "l"(a), "l"(b));
}
__device__ __forceinline__ float2 unpack2(unsigned long long v) {
    float lo, hi;
    asm("mov.b64 {%0, %1}, %2;" : "=f"(lo), "=f"(hi) : "l"(v));
    return make_float2(lo, hi);
}

// ---------------- kernel: transpose weights to k-major ----------------
__global__ void transpose_k(const float* __restrict__ e2, const float* __restrict__ c2,
                            const float* __restrict__ n1, const float* __restrict__ n2,
                            const float* __restrict__ e1, const float* __restrict__ c1) {
    int k = blockIdx.x;   // 0..255
    int f = threadIdx.x;  // 0..127
    g_n1wT[k*F_ + f] = n1[f*256 + k];
    g_e1T [k*F_ + f] = e1[f*258 + k];
    g_c1T [k*F_ + f] = c1[f*258 + k];
    if (k < F_) {
        g_w2eT[k*F_ + f] = e2[f*F_ + k];
        g_w2cT[k*F_ + f] = c2[f*F_ + k];
        g_n2wT[k*F_ + f] = n2[f*F_ + k];
    }
}

// ---------------- kernel: per-node precompute, RB rows per CTA ----------------
__global__ void pre_k(const float* __restrict__ x,  const float* __restrict__ h,
                      const float* __restrict__ lnh_w, const float* __restrict__ lnh_b,
                      const float* __restrict__ lnx_w, const float* __restrict__ lnx_b,
                      const float* __restrict__ e1b, const float* __restrict__ c1b) {
    int row0 = blockIdx.x * RB;
    int f    = threadIdx.x;
    int lane = f & 31, wp = f >> 5;
    __shared__ float hln[RB][F_];
    __shared__ float red[RB][4];

    float v[RB], d[RB];
    #pragma unroll
    for (int r = 0; r < RB; r++) v[r] = h[(row0 + r)*F_ + f];
    #pragma unroll
    for (int r = 0; r < RB; r++) {
        float s = v[r];
        #pragma unroll
        for (int o = 16; o; o >>= 1) s += __shfl_xor_sync(0xffffffffu, s, o);
        if (lane == 0) red[r][wp] = s;
    }
    __syncthreads();
    #pragma unroll
    for (int r = 0; r < RB; r++) {
        float mean = (red[r][0] + red[r][1] + red[r][2] + red[r][3]) * (1.f / F_);
        d[r] = v[r] - mean;
    }
    __syncthreads();
    #pragma unroll
    for (int r = 0; r < RB; r++) {
        float s2 = d[r] * d[r];
        #pragma unroll
        for (int o = 16; o; o >>= 1) s2 += __shfl_xor_sync(0xffffffffu, s2, o);
        if (lane == 0) red[r][wp] = s2;
    }
    __syncthreads();
    float gw = lnh_w[f], gb = lnh_b[f];
    #pragma unroll
    for (int r = 0; r < RB; r++) {
        float var  = (red[r][0] + red[r][1] + red[r][2] + red[r][3]) * (1.f / F_);
        float hl = d[r] * rsqrtf(var + 1e-5f) * gw + gb;
        hln[r][f] = hl;
        g_hln[(row0 + r)*F_ + f] = hl;
    }

    if (f < RB) {  // layernorm of x (3 comps) for row f
        int row = row0 + f;
        float a0 = x[row*3+0], a1 = x[row*3+1], a2 = x[row*3+2];
        float m  = (a0 + a1 + a2) * (1.f/3.f);
        float d0 = a0 - m, d1 = a1 - m, d2 = a2 - m;
        float vr = (d0*d0 + d1*d1 + d2*d2) * (1.f/3.f);
        float rs = rsqrtf(vr + 1e-5f);
        g_xln[row*3+0] = d0*rs*lnx_w[0] + lnx_b[0];
        g_xln[row*3+1] = d1*rs*lnx_w[1] + lnx_b[1];
        g_xln[row*3+2] = d2*rs*lnx_w[2] + lnx_b[2];
    }
    __syncthreads();

    // A/B decomposition of layer-1
    float ae[RB], be[RB], ac[RB], bc[RB];
    float eb = e1b[f], cb = c1b[f];
    #pragma unroll
    for (int r = 0; r < RB; r++) { ae[r] = eb; be[r] = 0.f; ac[r] = cb; bc[r] = 0.f; }
    #pragma unroll 4
    for (int k = 0; k < F_; k++) {
        float ea = g_e1T[k*F_ + f];
        float eB = g_e1T[(128 + k)*F_ + f];
        float ca = g_c1T[k*F_ + f];
        float cB = g_c1T[(128 + k)*F_ + f];
        #pragma unroll
        for (int r = 0; r < RB; r++) {
            float hk = hln[r][k];
            ae[r] += ea*hk; be[r] += eB*hk; ac[r] += ca*hk; bc[r] += cB*hk;
        }
    }
    #pragma unroll
    for (int r = 0; r < RB; r++) {
        g_Ae[(row0+r)*F_+f] = ae[r]; g_Be[(row0+r)*F_+f] = be[r];
        g_Ac[(row0+r)*F_+f] = ac[r]; g_Bc[(row0+r)*F_+f] = bc[r];
    }
}

// ---------------- the pair kernel: one CTA per (b,i), 512 threads ----------------
// SMEM floats: w2e 16384 | w2c 16384 | m1eT 128*68 | m1cT 128*68 | dsq 256 | r0 256
//              shift 768 | xi 8 | aggred 8*128 | csum 8*4  = 52520 floats = 210080 B
#define PAIR_SMEM_BYTES (52520 * 4)

__global__ __launch_bounds__(512, 1)
void pair_k(const float* __restrict__ x,   const float* __restrict__ x0,
            const float* __restrict__ e1w, const float* __restrict__ c1w,
            const float* __restrict__ e2b, const float* __restrict__ c2b,
            const float* __restrict__ eiw, const float* __restrict__ eib,
            const float* __restrict__ c3w, const float* __restrict__ c3b,
            float* __restrict__ out_x) {
    extern __shared__ float sm[];
    float* w2e      = sm;                  // [128][128] k-major
    float* w2c      = w2e + F_*F_;
    float* m1eT     = w2c + F_*F_;         // [128 k][68] (j in columns)
    float* m1cT     = m1eT + F_*MS;
    float* dsq_sh   = m1cT + F_*MS;        // [N_]
    float* r0_sh    = dsq_sh + N_;         // [N_]
    float* shift_sh = r0_sh + N_;          // [N_][3]
    float* xi_sh    = shift_sh + N_*3;     // x_i (3) at [0..2], x0_i (3) at [4..6]
    float* aggred   = xi_sh + 8;           // [8][128]
    float* csum_sh  = aggred + 8*F_;       // [8][4]

    int tid  = threadIdx.x;
    int rowI = blockIdx.x;
    int b    = rowI >> 8;
    int i    = rowI & 255;

    // stage both transposed weight matrices into SMEM
    for (int idx = tid; idx < F_*F_/4; idx += 512) {
        ((float4*)w2e)[idx] = ((const float4*)g_w2eT)[idx];
        ((float4*)w2c)[idx] = ((const float4*)g_w2cT)[idx];
    }

    // ---- phase 0 (hoisted): all N_ per-j geometric scalars, once ----
    if (tid < N_) {
        int j = tid;
        float xi0 = x[rowI*3+0], xi1 = x[rowI*3+1], xi2 = x[rowI*3+2];
        const float* xj = x + (b*N_ + j)*3;
        float dx = xi0 - xj[0];
        float dy = xi1 - xj[1];
        float dz = xi2 - xj[2];
        float ds = dx*dx + dy*dy + dz*dz;
        float r  = sqrtf(ds);
        float ri = __fdividef(1.f, r + 1.f);
        dsq_sh[j] = ds;
        shift_sh[j*3+0] = dx * ri;
        shift_sh[j*3+1] = dy * ri;
        shift_sh[j*3+2] = dz * ri;
        float yi0 = x0[rowI*3+0], yi1 = x0[rowI*3+1], yi2 = x0[rowI*3+2];
        const float* x0j = x0 + (b*N_ + j)*3;
        float ex = yi0 - x0j[0];
        float ey = yi1 - x0j[1];
        float ez = yi2 - x0j[2];
        r0_sh[j] = sqrtf(ex*ex + ey*ey + ez*ez);
    }

    // phase-1 mapping: thread handles feature f1, j's congruent to jg (mod 4)
    int f1 = tid >> 2;
    int jg = tid & 3;
    float ae  = g_Ae[rowI*F_ + f1];
    float ac  = g_Ac[rowI*F_ + f1];
    float wed = e1w[f1*258 + 256], wer = e1w[f1*258 + 257];
    float wcd = c1w[f1*258 + 256], wcr = c1w[f1*258 + 257];

    // GEMM mapping: 16 warps; wg = role (0 edge, 1 cor); wj = j-octet; lane tf = f quad
    int w  = tid >> 5, tf = tid & 31;
    int wg = w >> 3, wj = w & 7;
    const float* w2  = wg ? w2c : w2e;
    const float* m1T = wg ? m1cT : m1eT;
    float4 b2   = ((const float4*)(wg ? c2b : e2b))[tf];
    float4 wout = ((const float4*)(wg ? c3w : eiw))[tf];
    float  bout = wg ? c3b[0] : eib[0];

    float4 aggr = make_float4(0.f, 0.f, 0.f, 0.f);   // edge warps only
    float  csum_acc = 0.f;                            // cor warps only

    // ---- preload tile-0 layer-1 inputs into registers ----
    float be_reg[16], bc_reg[16];
    #pragma unroll
    for (int u = 0; u < 16; u++) {
        int j = jg + u*4;
        be_reg[u] = g_Be[(b*N_ + j)*F_ + f1];
        bc_reg[u] = g_Bc[(b*N_ + j)*F_ + f1];
    }

    __syncthreads();

    for (int t = 0; t < N_/TJ; t++) {
        int j0 = t * TJ;

        // ---- phase 1: layer-1 (decomposed) + silu -> transposed m1 tiles ----
        #pragma unroll
        for (int u = 0; u < 16; u++) {
            int jj = jg + u*4;
            float ds = dsq_sh[j0 + jj], rr = r0_sh[j0 + jj];
            float ze = ae + be_reg[u] + wed*ds + wer*rr;
            float zc = ac + bc_reg[u] + wcd*ds + wcr*rr;
            m1eT[f1*MS + jj] = siluf(ze);
            m1cT[f1*MS + jj] = siluf(zc);
        }
        // ---- preload next tile's inputs (drains under the GEMM) ----
        if (t < N_/TJ - 1) {
            #pragma unroll
            for (int u = 0; u < 16; u++) {
                int j = j0 + TJ + jg + u*4;
                be_reg[u] = g_Be[(b*N_ + j)*F_ + f1];
                bc_reg[u] = g_Bc[(b*N_ + j)*F_ + f1];
            }
        }
        __syncthreads();

        // ---- phase 2: role-split GEMM (each warp: 8 j x 128 f, lane: 8 j x 4 f) ----
        {
            unsigned long long acc[4][4];   // [j-pair][f]
            #pragma unroll
            for (int p = 0; p < 4; p++) {
                acc[p][0] = pack2(b2.x, b2.x);
                acc[p][1] = pack2(b2.y, b2.y);
                acc[p][2] = pack2(b2.z, b2.z);
                acc[p][3] = pack2(b2.w, b2.w);
            }
            #pragma unroll 4
            for (int k = 0; k < F_; k++) {
                float4 w4 = *(const float4*)&w2[k*F_ + tf*4];
                ulonglong2 mA = *(const ulonglong2*)&m1T[k*MS + wj*8];      // (j0,j1),(j2,j3)
                ulonglong2 mB = *(const ulonglong2*)&m1T[k*MS + wj*8 + 4];  // (j4,j5),(j6,j7)
                unsigned long long ws;
                ws = pack2(w4.x, w4.x);
                fma2(acc[0][0], mA.x, ws); fma2(acc[1][0], mA.y, ws);
                fma2(acc[2][0], mB.x, ws); fma2(acc[3][0], mB.y, ws);
                ws = pack2(w4.y, w4.y);
                fma2(acc[0][1], mA.x, ws); fma2(acc[1][1], mA.y, ws);
                fma2(acc[2][1], mB.x, ws); fma2(acc[3][1], mB.y, ws);
                ws = pack2(w4.z, w4.z);
                fma2(acc[0][2], mA.x, ws); fma2(acc[1][2], mA.y, ws);
                fma2(acc[2][2], mB.x, ws); fma2(acc[3][2], mB.y, ws);
                ws = pack2(w4.w, w4.w);
                fma2(acc[0][3], mA.x, ws); fma2(acc[1][3], mA.y, ws);
                fma2(acc[2][3], mB.x, ws); fma2(acc[3][3], mB.y, ws);
            }
            // epilogue: per j, silu -> 1-wide head -> gate/accumulate
            #pragma unroll
            for (int p = 0; p < 4; p++) {
                float2 h0 = unpack2(acc[p][0]);
                float2 h1 = unpack2(acc[p][1]);
                float2 h2 = unpack2(acc[p][2]);
                float2 h3 = unpack2(acc[p][3]);
                #pragma unroll
                for (int q = 0; q < 2; q++) {
                    int jj = wj*8 + p*2 + q;
                    float m0 = siluf(q ? h0.y : h0.x);
                    float m1 = siluf(q ? h1.y : h1.x);
                    float m2 = siluf(q ? h2.y : h2.x);
                    float m3 = siluf(q ? h3.y : h3.x);
                    float pdot = m0*wout.x + m1*wout.y + m2*wout.z + m3*wout.w;
                    #pragma unroll
                    for (int o = 16; o; o >>= 1)
                        pdot += __shfl_xor_sync(0xffffffffu, pdot, o);
                    if (wg == 0) {
                        float e = __fdividef(1.f, 1.f + __expf(-(pdot + bout)));
                        if (j0 + jj == i) e = 0.f;          // (1 - eye) mask
                        aggr.x += e*m0; aggr.y += e*m1; aggr.z += e*m2; aggr.w += e*m3;
                    } else {
                        float cw = pdot + bout;              // no activation on cor3
                        float sv = (tf < 3) ? shift_sh[(j0 + jj)*3 + tf] : 0.f;
                        csum_acc += cw * sv;                 // diagonal: shift == 0 exactly
                    }
                }
            }
        }
        __syncthreads();   // protect m1 before next tile overwrites
    }

    // ---- final reductions across warps ----
    if (wg == 0) *((float4*)&aggred[wj*F_ + tf*4]) = aggr;
    else if (tf < 3) csum_sh[wj*4 + tf] = csum_acc;
    __syncthreads();
    if (tid < F_) {
        float s = 0.f;
        #pragma unroll
        for (int ww = 0; ww < 8; ww++) s += aggred[ww*F_ + tid];
        g_agg[rowI*F_ + tid] = s;
    }
    if (tid < 3) {
        float s = 0.f;
        #pragma unroll
        for (int ww = 0; ww < 8; ww++) s += csum_sh[ww*4 + tid];
        out_x[rowI*3 + tid] = g_xln[rowI*3 + tid] + s;
    }
}

// ---------------- kernel: node update, RB rows per CTA ----------------
__global__ void node_k(const float* __restrict__ n1b, const float* __restrict__ n2b,
                       float* __restrict__ out_h) {
    int row0 = blockIdx.x * RB;
    int f    = threadIdx.x;
    __shared__ float hln[RB][F_], agg[RB][F_], nu[RB][F_];
    #pragma unroll
    for (int r = 0; r < RB; r++) {
        hln[r][f] = g_hln[(row0+r)*F_ + f];
        agg[r][f] = g_agg[(row0+r)*F_ + f];
    }
    __syncthreads();
    float z[RB];
    float b1 = n1b[f];
    #pragma unroll
    for (int r = 0; r < RB; r++) z[r] = b1;
    #pragma unroll 4
    for (int k = 0; k < F_; k++) {
        float w1 = g_n1wT[k*F_ + f];
        float w2 = g_n1wT[(128 + k)*F_ + f];
        #pragma unroll
        for (int r = 0; r < RB; r++) z[r] += w1*hln[r][k] + w2*agg[r][k];
    }
    #pragma unroll
    for (int r = 0; r < RB; r++) nu[r][f] = siluf(z[r]);
    __syncthreads();
    float o[RB];
    float b2 = n2b[f];
    #pragma unroll
    for (int r = 0; r < RB; r++) o[r] = b2;
    #pragma unroll 4
    for (int k = 0; k < F_; k++) {
        float wv = g_n2wT[k*F_ + f];
        #pragma unroll
        for (int r = 0; r < RB; r++) o[r] += wv*nu[r][k];
    }
    #pragma unroll
    for (int r = 0; r < RB; r++) out_h[(row0+r)*F_ + f] = hln[r][f] + o[r];
}

// ---------------- launch ----------------
extern "C" void kernel_launch(void* const* d_in, const int* in_sizes, int n_in,
                              void* d_out, int out_size) {
    const float* x      = (const float*)d_in[0];
    const float* h      = (const float*)d_in[1];
    const float* x0     = (const float*)d_in[2];
    const float* lnh_w  = (const float*)d_in[3];
    const float* lnh_b  = (const float*)d_in[4];
    const float* lnx_w  = (const float*)d_in[5];
    const float* lnx_b  = (const float*)d_in[6];
    const float* edg1_w = (const float*)d_in[7];
    const float* edg1_b = (const float*)d_in[8];
    const float* edg2_w = (const float*)d_in[9];
    const float* edg2_b = (const float*)d_in[10];
    const float* edgi_w = (const float*)d_in[11];
    const float* edgi_b = (const float*)d_in[12];
    const float* node1_w = (const float*)d_in[13];
    const float* node1_b = (const float*)d_in[14];
    const float* node2_w = (const float*)d_in[15];
    const float* node2_b = (const float*)d_in[16];
    const float* cor1_w = (const float*)d_in[17];
    const float* cor1_b = (const float*)d_in[18];
    const float* cor2_w = (const float*)d_in[19];
    const float* cor2_b = (const float*)d_in[20];
    const float* cor3_w = (const float*)d_in[21];
    const float* cor3_b = (const float*)d_in[22];

    float* out   = (float*)d_out;
    float* out_x = out;                 // (B,N,3) first
    float* out_h = out + BN_*3;         // then (B,N,F)

    cudaFuncSetAttribute(pair_k, cudaFuncAttributeMaxDynamicSharedMemorySize,
                         PAIR_SMEM_BYTES);

    transpose_k<<<256, F_>>>(edg2_w, cor2_w, node1_w, node2_w, edg1_w, cor1_w);
    pre_k<<<BN_/RB, F_>>>(x, h, lnh_w, lnh_b, lnx_w, lnx_b, edg1_b, cor1_b);
    pair_k<<<BN_, 512, PAIR_SMEM_BYTES>>>(x, x0, edg1_w, cor1_w,
                                          edg2_b, cor2_b, edgi_w, edgi_b,
                                          cor3_w, cor3_b, out_x);
    node_k<<<BN_/RB, F_>>>(node1_b, node2_b, out_h);
}

// round 10
// speedup vs baseline: 2.3420x; 1.0029x over previous
#include <cuda_runtime.h>

// Problem constants (B=4, N=256, F=128)
#define B_  4
#define N_  256
#define F_  128
#define BN_ (B_*N_)
#define TJ  64
#define MS  68        // m1T row stride (floats): stores land conflict-free, 16B aligned
#define RB  2         // rows per CTA in pre_k / node_k (512 CTAs -> good occupancy)

// ---------------- device scratch (static: no allocation allowed) ----------------
__device__ float g_hln[BN_*F_];   // layernormed h
__device__ float g_xln[BN_*3];    // layernormed x
__device__ float g_Ae[BN_*F_];    // edg1_w[:, :F] @ h_ln + edg1_b
__device__ float g_Be[BN_*F_];    // edg1_w[:, F:2F] @ h_ln
__device__ float g_Ac[BN_*F_];    // cor1 analogues
__device__ float g_Bc[BN_*F_];
__device__ float g_agg[BN_*F_];   // sum_j e*m
__device__ float g_w2eT[F_*F_];   // edg2_w transposed (k-major)
__device__ float g_w2cT[F_*F_];   // cor2_w transposed
__device__ float g_n1wT[256*F_];  // node1_w transposed (k-major, k=0..255)
__device__ float g_n2wT[F_*F_];   // node2_w transposed
__device__ float g_e1T[256*F_];   // edg1_w[:, :2F] transposed
__device__ float g_c1T[256*F_];   // cor1_w[:, :2F] transposed

__device__ __forceinline__ float siluf(float z) {
    return __fdividef(z, 1.f + __expf(-z));
}

// ---- packed fp32x2 FMA (FFMA2; ptxas never emits it from C++) ----
__device__ __forceinline__ unsigned long long pack2(float x, float y) {
    unsigned long long r;
    asm("mov.b64 %0, {%1, %2};" : "=l"(r) : "f"(x), "f"(y));
    return r;
}
__device__ __forceinline__ void fma2(unsigned long long &d,
                                     unsigned long long a, unsigned long long b) {
    asm("fma.rn.f32x2 %0, %1, %2, %0;" : "+l"(d) : "l"(a), "l"(b));
}
__device__ __forceinline__ float2 unpack2(unsigned long long v) {
    float lo, hi;
    asm("mov.b64 {%0, %1}, %2;" : "=f"(lo), "=f"(hi) : "l"(v));
    return make_float2(lo, hi);
}

// ---------------- kernel: transpose weights to k-major ----------------
__global__ void transpose_k(const float* __restrict__ e2, const float* __restrict__ c2,
                            const float* __restrict__ n1, const float* __restrict__ n2,
                            const float* __restrict__ e1, const float* __restrict__ c1) {
    int k = blockIdx.x;   // 0..255
    int f = threadIdx.x;  // 0..127
    g_n1wT[k*F_ + f] = n1[f*256 + k];
    g_e1T [k*F_ + f] = e1[f*258 + k];
    g_c1T [k*F_ + f] = c1[f*258 + k];
    if (k < F_) {
        g_w2eT[k*F_ + f] = e2[f*F_ + k];
        g_w2cT[k*F_ + f] = c2[f*F_ + k];
        g_n2wT[k*F_ + f] = n2[f*F_ + k];
    }
}

// ---------------- kernel: per-node precompute, RB rows per CTA ----------------
__global__ void pre_k(const float* __restrict__ x,  const float* __restrict__ h,
                      const float* __restrict__ lnh_w, const float* __restrict__ lnh_b,
                      const float* __restrict__ lnx_w, const float* __restrict__ lnx_b,
                      const float* __restrict__ e1b, const float* __restrict__ c1b) {
    int row0 = blockIdx.x * RB;
    int f    = threadIdx.x;
    int lane = f & 31, wp = f >> 5;
    __shared__ float hln[RB][F_];
    __shared__ float red[RB][4];

    float v[RB], d[RB];
    #pragma unroll
    for (int r = 0; r < RB; r++) v[r] = h[(row0 + r)*F_ + f];
    #pragma unroll
    for (int r = 0; r < RB; r++) {
        float s = v[r];
        #pragma unroll
        for (int o = 16; o; o >>= 1) s += __shfl_xor_sync(0xffffffffu, s, o);
        if (lane == 0) red[r][wp] = s;
    }
    __syncthreads();
    #pragma unroll
    for (int r = 0; r < RB; r++) {
        float mean = (red[r][0] + red[r][1] + red[r][2] + red[r][3]) * (1.f / F_);
        d[r] = v[r] - mean;
    }
    __syncthreads();
    #pragma unroll
    for (int r = 0; r < RB; r++) {
        float s2 = d[r] * d[r];
        #pragma unroll
        for (int o = 16; o; o >>= 1) s2 += __shfl_xor_sync(0xffffffffu, s2, o);
        if (lane == 0) red[r][wp] = s2;
    }
    __syncthreads();
    float gw = lnh_w[f], gb = lnh_b[f];
    #pragma unroll
    for (int r = 0; r < RB; r++) {
        float var  = (red[r][0] + red[r][1] + red[r][2] + red[r][3]) * (1.f / F_);
        float hl = d[r] * rsqrtf(var + 1e-5f) * gw + gb;
        hln[r][f] = hl;
        g_hln[(row0 + r)*F_ + f] = hl;
    }

    if (f < RB) {  // layernorm of x (3 comps) for row f
        int row = row0 + f;
        float a0 = x[row*3+0], a1 = x[row*3+1], a2 = x[row*3+2];
        float m  = (a0 + a1 + a2) * (1.f/3.f);
        float d0 = a0 - m, d1 = a1 - m, d2 = a2 - m;
        float vr = (d0*d0 + d1*d1 + d2*d2) * (1.f/3.f);
        float rs = rsqrtf(vr + 1e-5f);
        g_xln[row*3+0] = d0*rs*lnx_w[0] + lnx_b[0];
        g_xln[row*3+1] = d1*rs*lnx_w[1] + lnx_b[1];
        g_xln[row*3+2] = d2*rs*lnx_w[2] + lnx_b[2];
    }
    __syncthreads();

    // A/B decomposition of layer-1
    float ae[RB], be[RB], ac[RB], bc[RB];
    float eb = e1b[f], cb = c1b[f];
    #pragma unroll
    for (int r = 0; r < RB; r++) { ae[r] = eb; be[r] = 0.f; ac[r] = cb; bc[r] = 0.f; }
    #pragma unroll 4
    for (int k = 0; k < F_; k++) {
        float ea = g_e1T[k*F_ + f];
        float eB = g_e1T[(128 + k)*F_ + f];
        float ca = g_c1T[k*F_ + f];
        float cB = g_c1T[(128 + k)*F_ + f];
        #pragma unroll
        for (int r = 0; r < RB; r++) {
            float hk = hln[r][k];
            ae[r] += ea*hk; be[r] += eB*hk; ac[r] += ca*hk; bc[r] += cB*hk;
        }
    }
    #pragma unroll
    for (int r = 0; r < RB; r++) {
        g_Ae[(row0+r)*F_+f] = ae[r]; g_Be[(row0+r)*F_+f] = be[r];
        g_Ac[(row0+r)*F_+f] = ac[r]; g_Bc[(row0+r)*F_+f] = bc[r];
    }
}

// ---------------- the pair kernel: one CTA per (b,i), 512 threads ----------------
// SMEM floats: w2e 16384 | w2c 16384 | m1eT 128*68 | m1cT 128*68 | dsq 256 | r0 256
//              shift 768 | xi 8 | aggred 8*128 | csum 8*4  = 52520 floats = 210080 B
#define PAIR_SMEM_BYTES (52520 * 4)

__global__ __launch_bounds__(512, 1)
void pair_k(const float* __restrict__ x,   const float* __restrict__ x0,
            const float* __restrict__ e1w, const float* __restrict__ c1w,
            const float* __restrict__ e2b, const float* __restrict__ c2b,
            const float* __restrict__ eiw, const float* __restrict__ eib,
            const float* __restrict__ c3w, const float* __restrict__ c3b,
            float* __restrict__ out_x) {
    extern __shared__ float sm[];
    float* w2e      = sm;                  // [128][128] k-major
    float* w2c      = w2e + F_*F_;
    float* m1eT     = w2c + F_*F_;         // [128 k][68] (j in columns)
    float* m1cT     = m1eT + F_*MS;
    float* dsq_sh   = m1cT + F_*MS;        // [N_]
    float* r0_sh    = dsq_sh + N_;         // [N_]
    float* shift_sh = r0_sh + N_;          // [N_][3]
    float* xi_sh    = shift_sh + N_*3;     // x_i (3) at [0..2], x0_i (3) at [4..6]
    float* aggred   = xi_sh + 8;           // [8][128]
    float* csum_sh  = aggred + 8*F_;       // [8][4]

    int tid  = threadIdx.x;
    int rowI = blockIdx.x;
    int b    = rowI >> 8;
    int i    = rowI & 255;

    // stage both transposed weight matrices into SMEM
    for (int idx = tid; idx < F_*F_/4; idx += 512) {
        ((float4*)w2e)[idx] = ((const float4*)g_w2eT)[idx];
        ((float4*)w2c)[idx] = ((const float4*)g_w2cT)[idx];
    }

    // ---- phase 0 (hoisted): all N_ per-j geometric scalars, once ----
    if (tid < N_) {
        int j = tid;
        float xi0 = x[rowI*3+0], xi1 = x[rowI*3+1], xi2 = x[rowI*3+2];
        const float* xj = x + (b*N_ + j)*3;
        float dx = xi0 - xj[0];
        float dy = xi1 - xj[1];
        float dz = xi2 - xj[2];
        float ds = dx*dx + dy*dy + dz*dz;
        float r  = sqrtf(ds);
        float ri = __fdividef(1.f, r + 1.f);
        dsq_sh[j] = ds;
        shift_sh[j*3+0] = dx * ri;
        shift_sh[j*3+1] = dy * ri;
        shift_sh[j*3+2] = dz * ri;
        float yi0 = x0[rowI*3+0], yi1 = x0[rowI*3+1], yi2 = x0[rowI*3+2];
        const float* x0j = x0 + (b*N_ + j)*3;
        float ex = yi0 - x0j[0];
        float ey = yi1 - x0j[1];
        float ez = yi2 - x0j[2];
        r0_sh[j] = sqrtf(ex*ex + ey*ey + ez*ez);
    }

    // phase-1 mapping: thread handles feature f1, j's congruent to jg (mod 4)
    int f1 = tid >> 2;
    int jg = tid & 3;
    float ae  = g_Ae[rowI*F_ + f1];
    float ac  = g_Ac[rowI*F_ + f1];
    float wed = e1w[f1*258 + 256], wer = e1w[f1*258 + 257];
    float wcd = c1w[f1*258 + 256], wcr = c1w[f1*258 + 257];

    // GEMM mapping: 16 warps; wg = role (0 edge, 1 cor); wj = j-octet; lane tf = f quad
    int w  = tid >> 5, tf = tid & 31;
    int wg = w >> 3, wj = w & 7;
    const float* w2  = wg ? w2c : w2e;
    const float* m1T = wg ? m1cT : m1eT;
    float4 b2   = ((const float4*)(wg ? c2b : e2b))[tf];
    float4 wout = ((const float4*)(wg ? c3w : eiw))[tf];
    float  bout = wg ? c3b[0] : eib[0];

    float4 aggr = make_float4(0.f, 0.f, 0.f, 0.f);   // edge warps only
    float  csum_acc = 0.f;                            // cor warps only

    // ---- preload tile-0 layer-1 inputs into registers ----
    float be_reg[16], bc_reg[16];
    #pragma unroll
    for (int u = 0; u < 16; u++) {
        int j = jg + u*4;
        be_reg[u] = g_Be[(b*N_ + j)*F_ + f1];
        bc_reg[u] = g_Bc[(b*N_ + j)*F_ + f1];
    }

    __syncthreads();

    for (int t = 0; t < N_/TJ; t++) {
        int j0 = t * TJ;

        // ---- phase 1: layer-1 (decomposed) + silu -> transposed m1 tiles ----
        #pragma unroll
        for (int u = 0; u < 16; u++) {
            int jj = jg + u*4;
            float ds = dsq_sh[j0 + jj], rr = r0_sh[j0 + jj];
            float ze = ae + be_reg[u] + wed*ds + wer*rr;
            float zc = ac + bc_reg[u] + wcd*ds + wcr*rr;
            m1eT[f1*MS + jj] = siluf(ze);
            m1cT[f1*MS + jj] = siluf(zc);
        }
        // ---- preload next tile's inputs (drains under the GEMM) ----
        if (t < N_/TJ - 1) {
            #pragma unroll
            for (int u = 0; u < 16; u++) {
                int j = j0 + TJ + jg + u*4;
                be_reg[u] = g_Be[(b*N_ + j)*F_ + f1];
                bc_reg[u] = g_Bc[(b*N_ + j)*F_ + f1];
            }
        }
        __syncthreads();

        // ---- phase 2: role-split GEMM (each warp: 8 j x 128 f, lane: 8 j x 4 f) ----
        {
            unsigned long long acc[4][4];   // [j-pair][f]
            #pragma unroll
            for (int p = 0; p < 4; p++) {
                acc[p][0] = pack2(b2.x, b2.x);
                acc[p][1] = pack2(b2.y, b2.y);
                acc[p][2] = pack2(b2.z, b2.z);
                acc[p][3] = pack2(b2.w, b2.w);
            }
            #pragma unroll 4
            for (int k = 0; k < F_; k++) {
                float4 w4 = *(const float4*)&w2[k*F_ + tf*4];
                ulonglong2 mA = *(const ulonglong2*)&m1T[k*MS + wj*8];      // (j0,j1),(j2,j3)
                ulonglong2 mB = *(const ulonglong2*)&m1T[k*MS + wj*8 + 4];  // (j4,j5),(j6,j7)
                unsigned long long ws;
                ws = pack2(w4.x, w4.x);
                fma2(acc[0][0], mA.x, ws); fma2(acc[1][0], mA.y, ws);
                fma2(acc[2][0], mB.x, ws); fma2(acc[3][0], mB.y, ws);
                ws = pack2(w4.y, w4.y);
                fma2(acc[0][1], mA.x, ws); fma2(acc[1][1], mA.y, ws);
                fma2(acc[2][1], mB.x, ws); fma2(acc[3][1], mB.y, ws);
                ws = pack2(w4.z, w4.z);
                fma2(acc[0][2], mA.x, ws); fma2(acc[1][2], mA.y, ws);
                fma2(acc[2][2], mB.x, ws); fma2(acc[3][2], mB.y, ws);
                ws = pack2(w4.w, w4.w);
                fma2(acc[0][3], mA.x, ws); fma2(acc[1][3], mA.y, ws);
                fma2(acc[2][3], mB.x, ws); fma2(acc[3][3], mB.y, ws);
            }
            // epilogue: per j, silu -> 1-wide head -> gate/accumulate
            #pragma unroll
            for (int p = 0; p < 4; p++) {
                float2 h0 = unpack2(acc[p][0]);
                float2 h1 = unpack2(acc[p][1]);
                float2 h2 = unpack2(acc[p][2]);
                float2 h3 = unpack2(acc[p][3]);
                #pragma unroll
                for (int q = 0; q < 2; q++) {
                    int jj = wj*8 + p*2 + q;
                    float m0 = siluf(q ? h0.y : h0.x);
                    float m1 = siluf(q ? h1.y : h1.x);
                    float m2 = siluf(q ? h2.y : h2.x);
                    float m3 = siluf(q ? h3.y : h3.x);
                    float pdot = m0*wout.x + m1*wout.y + m2*wout.z + m3*wout.w;
                    #pragma unroll
                    for (int o = 16; o; o >>= 1)
                        pdot += __shfl_xor_sync(0xffffffffu, pdot, o);
                    if (wg == 0) {
                        float e = __fdividef(1.f, 1.f + __expf(-(pdot + bout)));
                        if (j0 + jj == i) e = 0.f;          // (1 - eye) mask
                        aggr.x += e*m0; aggr.y += e*m1; aggr.z += e*m2; aggr.w += e*m3;
                    } else {
                        float cw = pdot + bout;              // no activation on cor3
                        float sv = (tf < 3) ? shift_sh[(j0 + jj)*3 + tf] : 0.f;
                        csum_acc += cw * sv;                 // diagonal: shift == 0 exactly
                    }
                }
            }
        }
        __syncthreads();   // protect m1 before next tile overwrites
    }

    // ---- final reductions across warps ----
    if (wg == 0) *((float4*)&aggred[wj*F_ + tf*4]) = aggr;
    else if (tf < 3) csum_sh[wj*4 + tf] = csum_acc;
    __syncthreads();
    if (tid < F_) {
        float s = 0.f;
        #pragma unroll
        for (int ww = 0; ww < 8; ww++) s += aggred[ww*F_ + tid];
        g_agg[rowI*F_ + tid] = s;
    }
    if (tid < 3) {
        float s = 0.f;
        #pragma unroll
        for (int ww = 0; ww < 8; ww++) s += csum_sh[ww*4 + tid];
        out_x[rowI*3 + tid] = g_xln[rowI*3 + tid] + s;
    }
}

// ---------------- kernel: node update, RB rows per CTA ----------------
__global__ void node_k(const float* __restrict__ n1b, const float* __restrict__ n2b,
                       float* __restrict__ out_h) {
    int row0 = blockIdx.x * RB;
    int f    = threadIdx.x;
    __shared__ float hln[RB][F_], agg[RB][F_], nu[RB][F_];
    #pragma unroll
    for (int r = 0; r < RB; r++) {
        hln[r][f] = g_hln[(row0+r)*F_ + f];
        agg[r][f] = g_agg[(row0+r)*F_ + f];
    }
    __syncthreads();
    float z[RB];
    float b1 = n1b[f];
    #pragma unroll
    for (int r = 0; r < RB; r++) z[r] = b1;
    #pragma unroll 4
    for (int k = 0; k < F_; k++) {
        float w1 = g_n1wT[k*F_ + f];
        float w2 = g_n1wT[(128 + k)*F_ + f];
        #pragma unroll
        for (int r = 0; r < RB; r++) z[r] += w1*hln[r][k] + w2*agg[r][k];
    }
    #pragma unroll
    for (int r = 0; r < RB; r++) nu[r][f] = siluf(z[r]);
    __syncthreads();
    float o[RB];
    float b2 = n2b[f];
    #pragma unroll
    for (int r = 0; r < RB; r++) o[r] = b2;
    #pragma unroll 4
    for (int k = 0; k < F_; k++) {
        float wv = g_n2wT[k*F_ + f];
        #pragma unroll
        for (int r = 0; r < RB; r++) o[r] += wv*nu[r][k];
    }
    #pragma unroll
    for (int r = 0; r < RB; r++) out_h[(row0+r)*F_ + f] = hln[r][f] + o[r];
}

// ---------------- launch ----------------
extern "C" void kernel_launch(void* const* d_in, const int* in_sizes, int n_in,
                              void* d_out, int out_size) {
    const float* x      = (const float*)d_in[0];
    const float* h      = (const float*)d_in[1];
    const float* x0     = (const float*)d_in[2];
    const float* lnh_w  = (const float*)d_in[3];
    const float* lnh_b  = (const float*)d_in[4];
    const float* lnx_w  = (const float*)d_in[5];
    const float* lnx_b  = (const float*)d_in[6];
    const float* edg1_w = (const float*)d_in[7];
    const float* edg1_b = (const float*)d_in[8];
    const float* edg2_w = (const float*)d_in[9];
    const float* edg2_b = (const float*)d_in[10];
    const float* edgi_w = (const float*)d_in[11];
    const float* edgi_b = (const float*)d_in[12];
    const float* node1_w = (const float*)d_in[13];
    const float* node1_b = (const float*)d_in[14];
    const float* node2_w = (const float*)d_in[15];
    const float* node2_b = (const float*)d_in[16];
    const float* cor1_w = (const float*)d_in[17];
    const float* cor1_b = (const float*)d_in[18];
    const float* cor2_w = (const float*)d_in[19];
    const float* cor2_b = (const float*)d_in[20];
    const float* cor3_w = (const float*)d_in[21];
    const float* cor3_b = (const float*)d_in[22];

    float* out   = (float*)d_out;
    float* out_x = out;                 // (B,N,3) first
    float* out_h = out + BN_*3;         // then (B,N,F)

    cudaFuncSetAttribute(pair_k, cudaFuncAttributeMaxDynamicSharedMemorySize,
                         PAIR_SMEM_BYTES);

    transpose_k<<<256, F_>>>(edg2_w, cor2_w, node1_w, node2_w, edg1_w, cor1_w);
    pre_k<<<BN_/RB, F_>>>(x, h, lnh_w, lnh_b, lnx_w, lnx_b, edg1_b, cor1_b);
    pair_k<<<BN_, 512, PAIR_SMEM_BYTES>>>(x, x0, edg1_w, cor1_w,
                                          edg2_b, cor2_b, edgi_w, edgi_b,
                                          cor3_w, cor3_b, out_x);
    node_k<<<BN_/RB, F_>>>(node1_b, node2_b, out_h);
}